// round 1
// baseline (speedup 1.0000x reference)
#include <cuda_runtime.h>
#include <cstdint>

#define B_   16
#define T_   4096
#define D_   64
#define BR   64
#define BC   64
#define PAD  68            // smem row stride (floats) -> conflict-free fragment loads
#define NQB  (T_ / BR)

// Scratch for projected q (pre-scaled by 1/8), k, v — tf32-rounded fp32.
__device__ float g_q[B_ * T_ * D_];
__device__ float g_k[B_ * T_ * D_];
__device__ float g_v[B_ * T_ * D_];

__device__ __forceinline__ float to_tf32(float x) {
    uint32_t r;
    asm("cvt.rna.tf32.f32 %0, %1;" : "=r"(r) : "f"(x));
    return __uint_as_float(r);
}

// D(16x8) += A(16x8,row) * B(8x8,col)   tf32 inputs, f32 accum
__device__ __forceinline__ void mma8(float* c, const float* a, float b0, float b1) {
    asm volatile(
        "mma.sync.aligned.m16n8k8.row.col.f32.tf32.tf32.f32 "
        "{%0,%1,%2,%3}, {%4,%5,%6,%7}, {%8,%9}, {%0,%1,%2,%3};\n"
        : "+f"(c[0]), "+f"(c[1]), "+f"(c[2]), "+f"(c[3])
        : "r"(__float_as_uint(a[0])), "r"(__float_as_uint(a[1])),
          "r"(__float_as_uint(a[2])), "r"(__float_as_uint(a[3])),
          "r"(__float_as_uint(b0)),  "r"(__float_as_uint(b1)));
}

// ---------------------------------------------------------------------------
// QKV projection: q = (x @ Wq) * D^-0.5 ; k = x @ Wk ; v = x @ Wv
// One thread per (b,t) row. W staged in smem (pure broadcast reads).
// Outputs pre-rounded to tf32 so the attention MMAs get clean operands.
// ---------------------------------------------------------------------------
__global__ void __launch_bounds__(128) qkv_proj(const float* __restrict__ x,
                                                const float* __restrict__ Wq,
                                                const float* __restrict__ Wk,
                                                const float* __restrict__ Wv) {
    __shared__ float sW[64 * 64];
    const int tid = threadIdx.x;
    const int row = blockIdx.x * 128 + tid;

    // read this thread's x row once
    float xv[64];
    const float4* xr = (const float4*)(x + (size_t)row * D_);
#pragma unroll
    for (int i = 0; i < 16; i++) {
        float4 t = xr[i];
        xv[4 * i + 0] = t.x; xv[4 * i + 1] = t.y;
        xv[4 * i + 2] = t.z; xv[4 * i + 3] = t.w;
    }

#pragma unroll
    for (int m = 0; m < 3; m++) {
        const float* W = (m == 0) ? Wq : (m == 1) ? Wk : Wv;
        float* dst = ((m == 0) ? g_q : (m == 1) ? g_k : g_v) + (size_t)row * D_;
        const float scale = (m == 0) ? 0.125f : 1.0f;

        __syncthreads();
        for (int i = tid; i < 64 * 64; i += 128) sW[i] = W[i];
        __syncthreads();

#pragma unroll
        for (int jc = 0; jc < 64; jc += 16) {
            float acc[16];
#pragma unroll
            for (int j = 0; j < 16; j++) acc[j] = 0.f;
            for (int d = 0; d < 64; d++) {
                const float xd = xv[d];
#pragma unroll
                for (int j = 0; j < 16; j++) acc[j] += xd * sW[d * 64 + jc + j];
            }
#pragma unroll
            for (int j4 = 0; j4 < 16; j4 += 4) {
                float4 o;
                o.x = to_tf32(acc[j4 + 0] * scale);
                o.y = to_tf32(acc[j4 + 1] * scale);
                o.z = to_tf32(acc[j4 + 2] * scale);
                o.w = to_tf32(acc[j4 + 3] * scale);
                *(float4*)(dst + jc + j4) = o;
            }
        }
    }
}

// ---------------------------------------------------------------------------
// Flash attention, causal. CTA = (qb, b), Br=Bc=64, 4 warps (16 Q rows each).
// S = Q K^T and O += P V via m16n8k8 tf32 MMA; P staged through padded smem
// (own-warp rows only -> __syncwarp suffices). Heavy qb launched first.
// ---------------------------------------------------------------------------
__global__ void __launch_bounds__(128, 2) attn(float* __restrict__ out) {
    extern __shared__ float smem[];
    float* sK = smem;
    float* sV = smem + BC * PAD;
    float* sP = smem + 2 * BC * PAD;   // also Q staging buffer at start

    const int b    = blockIdx.y;
    const int qb   = (int)gridDim.x - 1 - (int)blockIdx.x;  // heavy-first
    const int tid  = threadIdx.x;
    const int warp = tid >> 5;
    const int lane = tid & 31;
    const int g    = lane >> 2;       // fragment group row
    const int i4   = lane & 3;        // fragment group col
    const int rA   = warp * 16 + g;   // this thread's local Q rows
    const int rB   = rA + 8;

    // --- stage Q block, read A-fragments once ---
    const float* Qg = g_q + ((size_t)(b * T_) + (size_t)qb * BR) * D_;
    for (int idx = tid; idx < BR * D_ / 4; idx += 128) {
        const int r = idx >> 4, c4 = (idx & 15) * 4;
        *(float4*)(sP + r * PAD + c4) = *(const float4*)(Qg + r * D_ + c4);
    }
    __syncthreads();
    float qf[8][4];
#pragma unroll
    for (int kk = 0; kk < 8; kk++) {
        qf[kk][0] = sP[rA * PAD + kk * 8 + i4];
        qf[kk][1] = sP[rB * PAD + kk * 8 + i4];
        qf[kk][2] = sP[rA * PAD + kk * 8 + i4 + 4];
        qf[kk][3] = sP[rB * PAD + kk * 8 + i4 + 4];
    }

    float o[8][4];
#pragma unroll
    for (int j = 0; j < 8; j++) { o[j][0] = o[j][1] = o[j][2] = o[j][3] = 0.f; }
    float m0 = -1e30f, m1 = -1e30f, l0 = 0.f, l1 = 0.f;

    const float* Kg = g_k + (size_t)b * T_ * D_;
    const float* Vg = g_v + (size_t)b * T_ * D_;

    for (int kb = 0; kb <= qb; kb++) {
        __syncthreads();   // previous iter's sK/sV reads done (and Q frag reads for kb=0)
        const float* Kp = Kg + (size_t)kb * BC * D_;
        const float* Vp = Vg + (size_t)kb * BC * D_;
        for (int idx = tid; idx < BC * D_ / 4; idx += 128) {
            const int r = idx >> 4, c4 = (idx & 15) * 4;
            *(float4*)(sK + r * PAD + c4) = *(const float4*)(Kp + r * D_ + c4);
            *(float4*)(sV + r * PAD + c4) = *(const float4*)(Vp + r * D_ + c4);
        }
        __syncthreads();

        // ---- S = Q K^T ----
        float s[8][4];
#pragma unroll
        for (int j = 0; j < 8; j++) {
            s[j][0] = s[j][1] = s[j][2] = s[j][3] = 0.f;
            const float* kr = sK + (j * 8 + g) * PAD + i4;   // conflict-free: bank=4g+i4
#pragma unroll
            for (int kk = 0; kk < 8; kk++)
                mma8(s[j], qf[kk], kr[kk * 8], kr[kk * 8 + 4]);
        }

        // ---- causal mask (diagonal block only) ----
        if (kb == qb) {
#pragma unroll
            for (int j = 0; j < 8; j++) {
                const int c0 = j * 8 + 2 * i4;
                if (c0     > rA) s[j][0] = -1e30f;
                if (c0 + 1 > rA) s[j][1] = -1e30f;
                if (c0     > rB) s[j][2] = -1e30f;
                if (c0 + 1 > rB) s[j][3] = -1e30f;
            }
        }

        // ---- online softmax ----
        float mx0 = -1e30f, mx1 = -1e30f;
#pragma unroll
        for (int j = 0; j < 8; j++) {
            mx0 = fmaxf(mx0, fmaxf(s[j][0], s[j][1]));
            mx1 = fmaxf(mx1, fmaxf(s[j][2], s[j][3]));
        }
        mx0 = fmaxf(mx0, __shfl_xor_sync(0xffffffffu, mx0, 1));
        mx0 = fmaxf(mx0, __shfl_xor_sync(0xffffffffu, mx0, 2));
        mx1 = fmaxf(mx1, __shfl_xor_sync(0xffffffffu, mx1, 1));
        mx1 = fmaxf(mx1, __shfl_xor_sync(0xffffffffu, mx1, 2));

        const float mn0 = fmaxf(m0, mx0), mn1 = fmaxf(m1, mx1);
        const float sc0 = __expf(m0 - mn0), sc1 = __expf(m1 - mn1);
        m0 = mn0; m1 = mn1;

        float rs0 = 0.f, rs1 = 0.f;
#pragma unroll
        for (int j = 0; j < 8; j++) {
            s[j][0] = __expf(s[j][0] - m0);
            s[j][1] = __expf(s[j][1] - m0);
            s[j][2] = __expf(s[j][2] - m1);
            s[j][3] = __expf(s[j][3] - m1);
            rs0 += s[j][0] + s[j][1];
            rs1 += s[j][2] + s[j][3];
        }
        rs0 += __shfl_xor_sync(0xffffffffu, rs0, 1);
        rs0 += __shfl_xor_sync(0xffffffffu, rs0, 2);
        rs1 += __shfl_xor_sync(0xffffffffu, rs1, 1);
        rs1 += __shfl_xor_sync(0xffffffffu, rs1, 2);
        l0 = l0 * sc0 + rs0;
        l1 = l1 * sc1 + rs1;

#pragma unroll
        for (int j = 0; j < 8; j++) {
            o[j][0] *= sc0; o[j][1] *= sc0;
            o[j][2] *= sc1; o[j][3] *= sc1;
        }

        // ---- P: C-layout -> A-layout via own-warp smem rows ----
#pragma unroll
        for (int j = 0; j < 8; j++) {
            const int c = j * 8 + 2 * i4;
            *(float2*)(sP + rA * PAD + c) = make_float2(to_tf32(s[j][0]), to_tf32(s[j][1]));
            *(float2*)(sP + rB * PAD + c) = make_float2(to_tf32(s[j][2]), to_tf32(s[j][3]));
        }
        __syncwarp();
        float pf[8][4];
#pragma unroll
        for (int kk = 0; kk < 8; kk++) {
            pf[kk][0] = sP[rA * PAD + kk * 8 + i4];
            pf[kk][1] = sP[rB * PAD + kk * 8 + i4];
            pf[kk][2] = sP[rA * PAD + kk * 8 + i4 + 4];
            pf[kk][3] = sP[rB * PAD + kk * 8 + i4 + 4];
        }

        // ---- O += P V ----
#pragma unroll
        for (int j = 0; j < 8; j++) {
#pragma unroll
            for (int kk = 0; kk < 8; kk++) {
                const float b0 = sV[(kk * 8 + i4)     * PAD + j * 8 + g];
                const float b1 = sV[(kk * 8 + i4 + 4) * PAD + j * 8 + g];
                mma8(o[j], pf[kk], b0, b1);
            }
        }
    }

    // ---- epilogue: normalize, store ----
    const float inv0 = 1.f / l0, inv1 = 1.f / l1;
    float* Og = out + ((size_t)(b * T_) + (size_t)qb * BR) * D_;
#pragma unroll
    for (int j = 0; j < 8; j++) {
        const int c = j * 8 + 2 * i4;
        *(float2*)(Og + rA * D_ + c) = make_float2(o[j][0] * inv0, o[j][1] * inv0);
        *(float2*)(Og + rB * D_ + c) = make_float2(o[j][2] * inv1, o[j][3] * inv1);
    }
}

extern "C" void kernel_launch(void* const* d_in, const int* in_sizes, int n_in,
                              void* d_out, int out_size) {
    const float* x  = (const float*)d_in[0];
    const float* Wq = (const float*)d_in[1];
    const float* Wk = (const float*)d_in[2];
    const float* Wv = (const float*)d_in[3];
    float* out = (float*)d_out;

    qkv_proj<<<(B_ * T_) / 128, 128>>>(x, Wq, Wk, Wv);

    const int smem_bytes = 3 * BC * PAD * (int)sizeof(float);  // 52224 B
    cudaFuncSetAttribute(attn, cudaFuncAttributeMaxDynamicSharedMemorySize, smem_bytes);
    attn<<<dim3(NQB, B_), 128, smem_bytes>>>(out);
}

// round 2
// speedup vs baseline: 1.0354x; 1.0354x over previous
#include <cuda_runtime.h>
#include <cstdint>

#define B_   16
#define T_   4096
#define D_   64
#define BR   128          // Q rows per CTA (8 warps x 16)
#define BC   64           // K/V rows per iteration
#define PAD  68           // smem row stride (floats) -> conflict-free fragment loads
#define NQB  (T_ / BR)    // 32

// Scratch for projected q (pre-scaled by 1/8), k, v — tf32-rounded fp32.
__device__ float g_q[B_ * T_ * D_];
__device__ float g_k[B_ * T_ * D_];
__device__ float g_v[B_ * T_ * D_];

__device__ __forceinline__ float to_tf32(float x) {
    uint32_t r;
    asm("cvt.rna.tf32.f32 %0, %1;" : "=r"(r) : "f"(x));
    return __uint_as_float(r);
}

// D(16x8) += A(16x8,row) * B(8x8,col)   tf32 inputs, f32 accum
__device__ __forceinline__ void mma8(float* c, const float* a, float b0, float b1) {
    asm volatile(
        "mma.sync.aligned.m16n8k8.row.col.f32.tf32.tf32.f32 "
        "{%0,%1,%2,%3}, {%4,%5,%6,%7}, {%8,%9}, {%0,%1,%2,%3};\n"
        : "+f"(c[0]), "+f"(c[1]), "+f"(c[2]), "+f"(c[3])
        : "r"(__float_as_uint(a[0])), "r"(__float_as_uint(a[1])),
          "r"(__float_as_uint(a[2])), "r"(__float_as_uint(a[3])),
          "r"(__float_as_uint(b0)),  "r"(__float_as_uint(b1)));
}

__device__ __forceinline__ void cp_async16(float* dst, const float* src) {
    uint32_t s = (uint32_t)__cvta_generic_to_shared(dst);
    asm volatile("cp.async.cg.shared.global [%0], [%1], 16;\n" :: "r"(s), "l"(src));
}
#define CP_COMMIT() asm volatile("cp.async.commit_group;\n" ::: "memory")
#define CP_WAIT1()  asm volatile("cp.async.wait_group 1;\n" ::: "memory")

// ---------------------------------------------------------------------------
// QKV projection: q = (x @ Wq) * D^-0.5 ; k = x @ Wk ; v = x @ Wv
// One thread per (b,t) row, 256 threads/CTA. W staged in smem, float4 reads.
// ---------------------------------------------------------------------------
__global__ void __launch_bounds__(256) qkv_proj(const float* __restrict__ x,
                                                const float* __restrict__ Wq,
                                                const float* __restrict__ Wk,
                                                const float* __restrict__ Wv) {
    __shared__ float4 sW[64 * 16];
    const int tid = threadIdx.x;
    const int row = blockIdx.x * 256 + tid;

    float xv[64];
    const float4* xr = (const float4*)(x + (size_t)row * D_);
#pragma unroll
    for (int i = 0; i < 16; i++) {
        float4 t = xr[i];
        xv[4 * i + 0] = t.x; xv[4 * i + 1] = t.y;
        xv[4 * i + 2] = t.z; xv[4 * i + 3] = t.w;
    }

#pragma unroll
    for (int m = 0; m < 3; m++) {
        const float* W = (m == 0) ? Wq : (m == 1) ? Wk : Wv;
        float* dst = ((m == 0) ? g_q : (m == 1) ? g_k : g_v) + (size_t)row * D_;
        const float scale = (m == 0) ? 0.125f : 1.0f;

        __syncthreads();
        for (int i = tid; i < 64 * 16; i += 256) sW[i] = ((const float4*)W)[i];
        __syncthreads();

#pragma unroll
        for (int jc = 0; jc < 4; jc++) {           // 16 output cols per chunk
            float acc[16];
#pragma unroll
            for (int j = 0; j < 16; j++) acc[j] = 0.f;
            for (int d = 0; d < 64; d++) {
                const float xd = xv[d];
                const float4 w0 = sW[d * 16 + jc * 4 + 0];
                const float4 w1 = sW[d * 16 + jc * 4 + 1];
                const float4 w2 = sW[d * 16 + jc * 4 + 2];
                const float4 w3 = sW[d * 16 + jc * 4 + 3];
                acc[0]  += xd * w0.x; acc[1]  += xd * w0.y; acc[2]  += xd * w0.z; acc[3]  += xd * w0.w;
                acc[4]  += xd * w1.x; acc[5]  += xd * w1.y; acc[6]  += xd * w1.z; acc[7]  += xd * w1.w;
                acc[8]  += xd * w2.x; acc[9]  += xd * w2.y; acc[10] += xd * w2.z; acc[11] += xd * w2.w;
                acc[12] += xd * w3.x; acc[13] += xd * w3.y; acc[14] += xd * w3.z; acc[15] += xd * w3.w;
            }
#pragma unroll
            for (int j4 = 0; j4 < 16; j4 += 4) {
                float4 o;
                o.x = to_tf32(acc[j4 + 0] * scale);
                o.y = to_tf32(acc[j4 + 1] * scale);
                o.z = to_tf32(acc[j4 + 2] * scale);
                o.w = to_tf32(acc[j4 + 3] * scale);
                *(float4*)(dst + jc * 16 + j4) = o;
            }
        }
    }
}

// ---------------------------------------------------------------------------
// Flash attention, causal. CTA = (qb, b), BR=128 (8 warps x 16 rows), BC=64.
// Double-buffered cp.async K/V. Heavy qb launched first.
// ---------------------------------------------------------------------------
__global__ void __launch_bounds__(256, 2) attn(float* __restrict__ out) {
    extern __shared__ float smem[];
    float* sK0 = smem;
    float* sV0 = smem + 1 * BC * PAD;
    float* sK1 = smem + 2 * BC * PAD;
    float* sV1 = smem + 3 * BC * PAD;
    float* sP  = smem + 4 * BC * PAD;   // BR x PAD; also Q staging buffer

    const int b    = blockIdx.y;
    const int qb   = NQB - 1 - (int)blockIdx.x;   // heavy-first
    const int tid  = threadIdx.x;
    const int warp = tid >> 5;
    const int lane = tid & 31;
    const int g    = lane >> 2;
    const int i4   = lane & 3;
    const int rA   = warp * 16 + g;
    const int rB   = rA + 8;
    const int last = 2 * qb + 1;

    const float* Kg = g_k + (size_t)b * T_ * D_;
    const float* Vg = g_v + (size_t)b * T_ * D_;

    // prefetch K/V stages 0 and 1 (last >= 1 always)
    {
        const float* Kp = Kg;
        const float* Vp = Vg;
#pragma unroll
        for (int i = 0; i < 4; i++) {
            const int idx = tid + 256 * i;
            const int r = idx >> 4, c4 = (idx & 15) * 4;
            cp_async16(sK0 + r * PAD + c4, Kp + r * D_ + c4);
            cp_async16(sV0 + r * PAD + c4, Vp + r * D_ + c4);
        }
        CP_COMMIT();
        Kp += BC * D_; Vp += BC * D_;
#pragma unroll
        for (int i = 0; i < 4; i++) {
            const int idx = tid + 256 * i;
            const int r = idx >> 4, c4 = (idx & 15) * 4;
            cp_async16(sK1 + r * PAD + c4, Kp + r * D_ + c4);
            cp_async16(sV1 + r * PAD + c4, Vp + r * D_ + c4);
        }
        CP_COMMIT();
    }

    // stage Q block into sP, read A-fragments once
    const float* Qg = g_q + ((size_t)b * T_ + (size_t)qb * BR) * D_;
#pragma unroll
    for (int i = 0; i < 8; i++) {
        const int idx = tid + 256 * i;
        const int r = idx >> 4, c4 = (idx & 15) * 4;
        *(float4*)(sP + r * PAD + c4) = *(const float4*)(Qg + r * D_ + c4);
    }
    __syncthreads();
    float qf[8][4];
#pragma unroll
    for (int kk = 0; kk < 8; kk++) {
        qf[kk][0] = sP[rA * PAD + kk * 8 + i4];
        qf[kk][1] = sP[rB * PAD + kk * 8 + i4];
        qf[kk][2] = sP[rA * PAD + kk * 8 + i4 + 4];
        qf[kk][3] = sP[rB * PAD + kk * 8 + i4 + 4];
    }

    float o[8][4];
#pragma unroll
    for (int j = 0; j < 8; j++) { o[j][0] = o[j][1] = o[j][2] = o[j][3] = 0.f; }
    float m0 = -1e30f, m1 = -1e30f, l0 = 0.f, l1 = 0.f;

    for (int kb = 0; kb <= last; kb++) {
        CP_WAIT1();
        __syncthreads();   // stage data visible CTA-wide; sP reads done
        const float* sKb = (kb & 1) ? sK1 : sK0;
        const float* sVb = (kb & 1) ? sV1 : sV0;

        // warps fully above the diagonal on the final block: skip compute
        const bool active = !(kb == 2 * qb + 1 && warp < 4);
        if (active) {
            // ---- S = Q K^T ----
            float s[8][4];
#pragma unroll
            for (int j = 0; j < 8; j++) {
                s[j][0] = s[j][1] = s[j][2] = s[j][3] = 0.f;
                const float* kr = sKb + (j * 8 + g) * PAD + i4;   // banks 4g+i4: conflict-free
#pragma unroll
                for (int kk = 0; kk < 8; kk++)
                    mma8(s[j], qf[kk], kr[kk * 8], kr[kk * 8 + 4]);
            }

            // ---- causal mask (only blocks touching the diagonal) ----
            if (kb >= 2 * qb) {
                const int cb = (kb - 2 * qb) * 64;
#pragma unroll
                for (int j = 0; j < 8; j++) {
                    const int c0 = j * 8 + 2 * i4 + cb;
                    if (c0     > rA) s[j][0] = -1e30f;
                    if (c0 + 1 > rA) s[j][1] = -1e30f;
                    if (c0     > rB) s[j][2] = -1e30f;
                    if (c0 + 1 > rB) s[j][3] = -1e30f;
                }
            }

            // ---- online softmax ----
            float mx0 = -1e30f, mx1 = -1e30f;
#pragma unroll
            for (int j = 0; j < 8; j++) {
                mx0 = fmaxf(mx0, fmaxf(s[j][0], s[j][1]));
                mx1 = fmaxf(mx1, fmaxf(s[j][2], s[j][3]));
            }
            mx0 = fmaxf(mx0, __shfl_xor_sync(0xffffffffu, mx0, 1));
            mx0 = fmaxf(mx0, __shfl_xor_sync(0xffffffffu, mx0, 2));
            mx1 = fmaxf(mx1, __shfl_xor_sync(0xffffffffu, mx1, 1));
            mx1 = fmaxf(mx1, __shfl_xor_sync(0xffffffffu, mx1, 2));

            const float mn0 = fmaxf(m0, mx0), mn1 = fmaxf(m1, mx1);
            const float sc0 = __expf(m0 - mn0), sc1 = __expf(m1 - mn1);
            m0 = mn0; m1 = mn1;

            float rs0 = 0.f, rs1 = 0.f;
#pragma unroll
            for (int j = 0; j < 8; j++) {
                s[j][0] = __expf(s[j][0] - m0);
                s[j][1] = __expf(s[j][1] - m0);
                s[j][2] = __expf(s[j][2] - m1);
                s[j][3] = __expf(s[j][3] - m1);
                rs0 += s[j][0] + s[j][1];
                rs1 += s[j][2] + s[j][3];
            }
            rs0 += __shfl_xor_sync(0xffffffffu, rs0, 1);
            rs0 += __shfl_xor_sync(0xffffffffu, rs0, 2);
            rs1 += __shfl_xor_sync(0xffffffffu, rs1, 1);
            rs1 += __shfl_xor_sync(0xffffffffu, rs1, 2);
            l0 = l0 * sc0 + rs0;
            l1 = l1 * sc1 + rs1;

#pragma unroll
            for (int j = 0; j < 8; j++) {
                o[j][0] *= sc0; o[j][1] *= sc0;
                o[j][2] *= sc1; o[j][3] *= sc1;
            }

            // ---- P: C-layout -> A-layout via own-warp smem rows ----
#pragma unroll
            for (int j = 0; j < 8; j++) {
                const int c = j * 8 + 2 * i4;
                *(float2*)(sP + rA * PAD + c) = make_float2(to_tf32(s[j][0]), to_tf32(s[j][1]));
                *(float2*)(sP + rB * PAD + c) = make_float2(to_tf32(s[j][2]), to_tf32(s[j][3]));
            }
            __syncwarp();
#pragma unroll
            for (int kk = 0; kk < 8; kk++) {   // reuse s[] as A fragments of P
                s[kk][0] = sP[rA * PAD + kk * 8 + i4];
                s[kk][1] = sP[rB * PAD + kk * 8 + i4];
                s[kk][2] = sP[rA * PAD + kk * 8 + i4 + 4];
                s[kk][3] = sP[rB * PAD + kk * 8 + i4 + 4];
            }

            // ---- O += P V ----
#pragma unroll
            for (int j = 0; j < 8; j++) {
#pragma unroll
                for (int kk = 0; kk < 8; kk++) {
                    const float b0 = sVb[(kk * 8 + i4)     * PAD + j * 8 + g];
                    const float b1 = sVb[(kk * 8 + i4 + 4) * PAD + j * 8 + g];
                    mma8(o[j], s[kk], b0, b1);
                }
            }
        }

        __syncthreads();   // all warps done reading buf (kb&1) before refill
        if (kb + 2 <= last) {
            float* dK = (kb & 1) ? sK1 : sK0;
            float* dV = (kb & 1) ? sV1 : sV0;
            const float* Kp = Kg + (size_t)(kb + 2) * BC * D_;
            const float* Vp = Vg + (size_t)(kb + 2) * BC * D_;
#pragma unroll
            for (int i = 0; i < 4; i++) {
                const int idx = tid + 256 * i;
                const int r = idx >> 4, c4 = (idx & 15) * 4;
                cp_async16(dK + r * PAD + c4, Kp + r * D_ + c4);
                cp_async16(dV + r * PAD + c4, Vp + r * D_ + c4);
            }
        }
        CP_COMMIT();   // commit every iter (possibly empty) to keep group accounting uniform
    }

    // ---- epilogue: normalize, store ----
    const float inv0 = 1.f / l0, inv1 = 1.f / l1;
    float* Og = out + ((size_t)b * T_ + (size_t)qb * BR) * D_;
#pragma unroll
    for (int j = 0; j < 8; j++) {
        const int c = j * 8 + 2 * i4;
        *(float2*)(Og + rA * D_ + c) = make_float2(o[j][0] * inv0, o[j][1] * inv0);
        *(float2*)(Og + rB * D_ + c) = make_float2(o[j][2] * inv1, o[j][3] * inv1);
    }
}

extern "C" void kernel_launch(void* const* d_in, const int* in_sizes, int n_in,
                              void* d_out, int out_size) {
    const float* x  = (const float*)d_in[0];
    const float* Wq = (const float*)d_in[1];
    const float* Wk = (const float*)d_in[2];
    const float* Wv = (const float*)d_in[3];
    float* out = (float*)d_out;

    qkv_proj<<<(B_ * T_) / 256, 256>>>(x, Wq, Wk, Wv);

    const int smem_bytes = (4 * BC * PAD + BR * PAD) * (int)sizeof(float);  // 104448 B
    cudaFuncSetAttribute(attn, cudaFuncAttributeMaxDynamicSharedMemorySize, smem_bytes);
    attn<<<dim3(NQB, B_), 256, smem_bytes>>>(out);
}

// round 3
// speedup vs baseline: 1.0431x; 1.0075x over previous
#include <cuda_runtime.h>
#include <cstdint>

#define B_   16
#define T_   4096
#define D_   64
#define BR   128          // Q rows per CTA (8 warps x 16)
#define BC   64           // K/V rows per iteration
#define PAD  68           // smem row stride (floats) -> conflict-free fragment loads
#define NQB  (T_ / BR)    // 32

// Scratch for projected q (pre-scaled by 1/8), k, v — tf32-rounded fp32.
__device__ float g_q[B_ * T_ * D_];
__device__ float g_k[B_ * T_ * D_];
__device__ float g_v[B_ * T_ * D_];

__device__ __forceinline__ float to_tf32(float x) {
    uint32_t r;
    asm("cvt.rna.tf32.f32 %0, %1;" : "=r"(r) : "f"(x));
    return __uint_as_float(r);
}

// D(16x8) += A(16x8,row) * B(8x8,col)   tf32 inputs, f32 accum
__device__ __forceinline__ void mma8(float* c, const float* a, float b0, float b1) {
    asm volatile(
        "mma.sync.aligned.m16n8k8.row.col.f32.tf32.tf32.f32 "
        "{%0,%1,%2,%3}, {%4,%5,%6,%7}, {%8,%9}, {%0,%1,%2,%3};\n"
        : "+f"(c[0]), "+f"(c[1]), "+f"(c[2]), "+f"(c[3])
        : "r"(__float_as_uint(a[0])), "r"(__float_as_uint(a[1])),
          "r"(__float_as_uint(a[2])), "r"(__float_as_uint(a[3])),
          "r"(__float_as_uint(b0)),  "r"(__float_as_uint(b1)));
}

__device__ __forceinline__ void cp_async16(float* dst, const float* src) {
    uint32_t s = (uint32_t)__cvta_generic_to_shared(dst);
    asm volatile("cp.async.cg.shared.global [%0], [%1], 16;\n" :: "r"(s), "l"(src));
}
#define CP_COMMIT() asm volatile("cp.async.commit_group;\n" ::: "memory")
#define CP_WAIT1()  asm volatile("cp.async.wait_group 1;\n" ::: "memory")

// ---------------------------------------------------------------------------
// QKV projection: q = (x @ Wq) * D^-0.5 ; k = x @ Wk ; v = x @ Wv
// One thread per (b,t) row, 256 threads/CTA. W staged in smem, float4 reads.
// ---------------------------------------------------------------------------
__global__ void __launch_bounds__(256) qkv_proj(const float* __restrict__ x,
                                                const float* __restrict__ Wq,
                                                const float* __restrict__ Wk,
                                                const float* __restrict__ Wv) {
    __shared__ float4 sW[64 * 16];
    const int tid = threadIdx.x;
    const int row = blockIdx.x * 256 + tid;

    float xv[64];
    const float4* xr = (const float4*)(x + (size_t)row * D_);
#pragma unroll
    for (int i = 0; i < 16; i++) {
        float4 t = xr[i];
        xv[4 * i + 0] = t.x; xv[4 * i + 1] = t.y;
        xv[4 * i + 2] = t.z; xv[4 * i + 3] = t.w;
    }

#pragma unroll
    for (int m = 0; m < 3; m++) {
        const float* W = (m == 0) ? Wq : (m == 1) ? Wk : Wv;
        float* dst = ((m == 0) ? g_q : (m == 1) ? g_k : g_v) + (size_t)row * D_;
        const float scale = (m == 0) ? 0.125f : 1.0f;

        __syncthreads();
        for (int i = tid; i < 64 * 16; i += 256) sW[i] = ((const float4*)W)[i];
        __syncthreads();

#pragma unroll
        for (int jc = 0; jc < 4; jc++) {           // 16 output cols per chunk
            float acc[16];
#pragma unroll
            for (int j = 0; j < 16; j++) acc[j] = 0.f;
            for (int d = 0; d < 64; d++) {
                const float xd = xv[d];
                const float4 w0 = sW[d * 16 + jc * 4 + 0];
                const float4 w1 = sW[d * 16 + jc * 4 + 1];
                const float4 w2 = sW[d * 16 + jc * 4 + 2];
                const float4 w3 = sW[d * 16 + jc * 4 + 3];
                acc[0]  += xd * w0.x; acc[1]  += xd * w0.y; acc[2]  += xd * w0.z; acc[3]  += xd * w0.w;
                acc[4]  += xd * w1.x; acc[5]  += xd * w1.y; acc[6]  += xd * w1.z; acc[7]  += xd * w1.w;
                acc[8]  += xd * w2.x; acc[9]  += xd * w2.y; acc[10] += xd * w2.z; acc[11] += xd * w2.w;
                acc[12] += xd * w3.x; acc[13] += xd * w3.y; acc[14] += xd * w3.z; acc[15] += xd * w3.w;
            }
#pragma unroll
            for (int j4 = 0; j4 < 16; j4 += 4) {
                float4 o;
                o.x = to_tf32(acc[j4 + 0] * scale);
                o.y = to_tf32(acc[j4 + 1] * scale);
                o.z = to_tf32(acc[j4 + 2] * scale);
                o.w = to_tf32(acc[j4 + 3] * scale);
                *(float4*)(dst + jc * 16 + j4) = o;
            }
        }
    }
}

// ---------------------------------------------------------------------------
// Flash attention, causal. CTA = (qb, b), BR=128 (8 warps x 16 rows), BC=64.
// Double-buffered cp.async K/V. Heavy qb launched first.
// ---------------------------------------------------------------------------
__global__ void __launch_bounds__(256, 2) attn(float* __restrict__ out) {
    extern __shared__ float smem[];
    float* sK0 = smem;
    float* sV0 = smem + 1 * BC * PAD;
    float* sK1 = smem + 2 * BC * PAD;
    float* sV1 = smem + 3 * BC * PAD;
    float* sP  = smem + 4 * BC * PAD;   // BR x PAD; also Q staging buffer

    const int b    = blockIdx.y;
    const int qb   = NQB - 1 - (int)blockIdx.x;   // heavy-first
    const int tid  = threadIdx.x;
    const int warp = tid >> 5;
    const int lane = tid & 31;
    const int g    = lane >> 2;
    const int i4   = lane & 3;
    const int rA   = warp * 16 + g;
    const int rB   = rA + 8;
    const int last = 2 * qb + 1;

    const float* Kg = g_k + (size_t)b * T_ * D_;
    const float* Vg = g_v + (size_t)b * T_ * D_;

    // prefetch K/V stages 0 and 1 (last >= 1 always)
    {
        const float* Kp = Kg;
        const float* Vp = Vg;
#pragma unroll
        for (int i = 0; i < 4; i++) {
            const int idx = tid + 256 * i;
            const int r = idx >> 4, c4 = (idx & 15) * 4;
            cp_async16(sK0 + r * PAD + c4, Kp + r * D_ + c4);
            cp_async16(sV0 + r * PAD + c4, Vp + r * D_ + c4);
        }
        CP_COMMIT();
        Kp += BC * D_; Vp += BC * D_;
#pragma unroll
        for (int i = 0; i < 4; i++) {
            const int idx = tid + 256 * i;
            const int r = idx >> 4, c4 = (idx & 15) * 4;
            cp_async16(sK1 + r * PAD + c4, Kp + r * D_ + c4);
            cp_async16(sV1 + r * PAD + c4, Vp + r * D_ + c4);
        }
        CP_COMMIT();
    }

    // stage Q block into sP, read A-fragments once
    const float* Qg = g_q + ((size_t)b * T_ + (size_t)qb * BR) * D_;
#pragma unroll
    for (int i = 0; i < 8; i++) {
        const int idx = tid + 256 * i;
        const int r = idx >> 4, c4 = (idx & 15) * 4;
        *(float4*)(sP + r * PAD + c4) = *(const float4*)(Qg + r * D_ + c4);
    }
    __syncthreads();
    float qf[8][4];
#pragma unroll
    for (int kk = 0; kk < 8; kk++) {
        qf[kk][0] = sP[rA * PAD + kk * 8 + i4];
        qf[kk][1] = sP[rB * PAD + kk * 8 + i4];
        qf[kk][2] = sP[rA * PAD + kk * 8 + i4 + 4];
        qf[kk][3] = sP[rB * PAD + kk * 8 + i4 + 4];
    }

    float o[8][4];
#pragma unroll
    for (int j = 0; j < 8; j++) { o[j][0] = o[j][1] = o[j][2] = o[j][3] = 0.f; }
    float m0 = -1e30f, m1 = -1e30f, l0 = 0.f, l1 = 0.f;

    for (int kb = 0; kb <= last; kb++) {
        CP_WAIT1();
        __syncthreads();   // stage data visible CTA-wide; sP reads done
        const float* sKb = (kb & 1) ? sK1 : sK0;
        const float* sVb = (kb & 1) ? sV1 : sV0;

        // warps fully above the diagonal on the final block: skip compute
        const bool active = !(kb == 2 * qb + 1 && warp < 4);
        if (active) {
            // ---- S = Q K^T ----
            float s[8][4];
#pragma unroll
            for (int j = 0; j < 8; j++) {
                s[j][0] = s[j][1] = s[j][2] = s[j][3] = 0.f;
                const float* kr = sKb + (j * 8 + g) * PAD + i4;   // banks 4g+i4: conflict-free
#pragma unroll
                for (int kk = 0; kk < 8; kk++)
                    mma8(s[j], qf[kk], kr[kk * 8], kr[kk * 8 + 4]);
            }

            // ---- causal mask (only blocks touching the diagonal) ----
            if (kb >= 2 * qb) {
                const int cb = (kb - 2 * qb) * 64;
#pragma unroll
                for (int j = 0; j < 8; j++) {
                    const int c0 = j * 8 + 2 * i4 + cb;
                    if (c0     > rA) s[j][0] = -1e30f;
                    if (c0 + 1 > rA) s[j][1] = -1e30f;
                    if (c0     > rB) s[j][2] = -1e30f;
                    if (c0 + 1 > rB) s[j][3] = -1e30f;
                }
            }

            // ---- online softmax ----
            float mx0 = -1e30f, mx1 = -1e30f;
#pragma unroll
            for (int j = 0; j < 8; j++) {
                mx0 = fmaxf(mx0, fmaxf(s[j][0], s[j][1]));
                mx1 = fmaxf(mx1, fmaxf(s[j][2], s[j][3]));
            }
            mx0 = fmaxf(mx0, __shfl_xor_sync(0xffffffffu, mx0, 1));
            mx0 = fmaxf(mx0, __shfl_xor_sync(0xffffffffu, mx0, 2));
            mx1 = fmaxf(mx1, __shfl_xor_sync(0xffffffffu, mx1, 1));
            mx1 = fmaxf(mx1, __shfl_xor_sync(0xffffffffu, mx1, 2));

            const float mn0 = fmaxf(m0, mx0), mn1 = fmaxf(m1, mx1);
            const float sc0 = __expf(m0 - mn0), sc1 = __expf(m1 - mn1);
            m0 = mn0; m1 = mn1;

            float rs0 = 0.f, rs1 = 0.f;
#pragma unroll
            for (int j = 0; j < 8; j++) {
                s[j][0] = __expf(s[j][0] - m0);
                s[j][1] = __expf(s[j][1] - m0);
                s[j][2] = __expf(s[j][2] - m1);
                s[j][3] = __expf(s[j][3] - m1);
                rs0 += s[j][0] + s[j][1];
                rs1 += s[j][2] + s[j][3];
            }
            rs0 += __shfl_xor_sync(0xffffffffu, rs0, 1);
            rs0 += __shfl_xor_sync(0xffffffffu, rs0, 2);
            rs1 += __shfl_xor_sync(0xffffffffu, rs1, 1);
            rs1 += __shfl_xor_sync(0xffffffffu, rs1, 2);
            l0 = l0 * sc0 + rs0;
            l1 = l1 * sc1 + rs1;

#pragma unroll
            for (int j = 0; j < 8; j++) {
                o[j][0] *= sc0; o[j][1] *= sc0;
                o[j][2] *= sc1; o[j][3] *= sc1;
            }

            // ---- P: C-layout -> A-layout via own-warp smem rows ----
#pragma unroll
            for (int j = 0; j < 8; j++) {
                const int c = j * 8 + 2 * i4;
                *(float2*)(sP + rA * PAD + c) = make_float2(to_tf32(s[j][0]), to_tf32(s[j][1]));
                *(float2*)(sP + rB * PAD + c) = make_float2(to_tf32(s[j][2]), to_tf32(s[j][3]));
            }
            __syncwarp();
#pragma unroll
            for (int kk = 0; kk < 8; kk++) {   // reuse s[] as A fragments of P
                s[kk][0] = sP[rA * PAD + kk * 8 + i4];
                s[kk][1] = sP[rB * PAD + kk * 8 + i4];
                s[kk][2] = sP[rA * PAD + kk * 8 + i4 + 4];
                s[kk][3] = sP[rB * PAD + kk * 8 + i4 + 4];
            }

            // ---- O += P V ----
#pragma unroll
            for (int j = 0; j < 8; j++) {
#pragma unroll
                for (int kk = 0; kk < 8; kk++) {
                    const float b0 = sVb[(kk * 8 + i4)     * PAD + j * 8 + g];
                    const float b1 = sVb[(kk * 8 + i4 + 4) * PAD + j * 8 + g];
                    mma8(o[j], s[kk], b0, b1);
                }
            }
        }

        __syncthreads();   // all warps done reading buf (kb&1) before refill
        if (kb + 2 <= last) {
            float* dK = (kb & 1) ? sK1 : sK0;
            float* dV = (kb & 1) ? sV1 : sV0;
            const float* Kp = Kg + (size_t)(kb + 2) * BC * D_;
            const float* Vp = Vg + (size_t)(kb + 2) * BC * D_;
#pragma unroll
            for (int i = 0; i < 4; i++) {
                const int idx = tid + 256 * i;
                const int r = idx >> 4, c4 = (idx & 15) * 4;
                cp_async16(dK + r * PAD + c4, Kp + r * D_ + c4);
                cp_async16(dV + r * PAD + c4, Vp + r * D_ + c4);
            }
        }
        CP_COMMIT();   // commit every iter (possibly empty) to keep group accounting uniform
    }

    // ---- epilogue: normalize, store ----
    const float inv0 = 1.f / l0, inv1 = 1.f / l1;
    float* Og = out + ((size_t)b * T_ + (size_t)qb * BR) * D_;
#pragma unroll
    for (int j = 0; j < 8; j++) {
        const int c = j * 8 + 2 * i4;
        *(float2*)(Og + rA * D_ + c) = make_float2(o[j][0] * inv0, o[j][1] * inv0);
        *(float2*)(Og + rB * D_ + c) = make_float2(o[j][2] * inv1, o[j][3] * inv1);
    }
}

extern "C" void kernel_launch(void* const* d_in, const int* in_sizes, int n_in,
                              void* d_out, int out_size) {
    const float* x  = (const float*)d_in[0];
    const float* Wq = (const float*)d_in[1];
    const float* Wk = (const float*)d_in[2];
    const float* Wv = (const float*)d_in[3];
    float* out = (float*)d_out;

    qkv_proj<<<(B_ * T_) / 256, 256>>>(x, Wq, Wk, Wv);

    const int smem_bytes = (4 * BC * PAD + BR * PAD) * (int)sizeof(float);  // 104448 B
    cudaFuncSetAttribute(attn, cudaFuncAttributeMaxDynamicSharedMemorySize, smem_bytes);
    attn<<<dim3(NQB, B_), 256, smem_bytes>>>(out);
}

// round 5
// speedup vs baseline: 2.0920x; 2.0055x over previous
#include <cuda_runtime.h>
#include <cuda_fp16.h>
#include <cstdint>

#define B_   16
#define T_   4096
#define D_   64
#define BR   64
#define BC   64
#define STR  72            // smem row stride in halfs -> conflict-free frag loads
#define NQB  (T_ / BR)     // 64

// Projected q (pre-scaled by 1/8), k as [B][T][D]; V transposed as [B][D][T]. All fp16.
__device__ __half g_q [B_ * T_ * D_];
__device__ __half g_k [B_ * T_ * D_];
__device__ __half g_vt[B_ * D_ * T_];

static __device__ __forceinline__ uint32_t f22h(float x, float y) {
    __half2 h = __floats2half2_rn(x, y);
    return *(uint32_t*)&h;
}

// D(16x8,f32) += A(16x16,f16,row) * B(16x8,f16,col)
static __device__ __forceinline__ void mma16(float* c, const uint32_t* a,
                                             uint32_t b0, uint32_t b1) {
    asm volatile(
        "mma.sync.aligned.m16n8k16.row.col.f32.f16.f16.f32 "
        "{%0,%1,%2,%3}, {%4,%5,%6,%7}, {%8,%9}, {%0,%1,%2,%3};\n"
        : "+f"(c[0]), "+f"(c[1]), "+f"(c[2]), "+f"(c[3])
        : "r"(a[0]), "r"(a[1]), "r"(a[2]), "r"(a[3]), "r"(b0), "r"(b1));
}

static __device__ __forceinline__ void cp16(__half* dst, const __half* src) {
    uint32_t s = (uint32_t)__cvta_generic_to_shared(dst);
    asm volatile("cp.async.cg.shared.global [%0], [%1], 16;" :: "r"(s), "l"(src));
}
#define CP_COMMIT() asm volatile("cp.async.commit_group;" ::: "memory")
#define CP_WAIT1()  asm volatile("cp.async.wait_group 1;"  ::: "memory")

// ---------------------------------------------------------------------------
// QKV projection: q = (x@Wq)/8, k = x@Wk (both [b][t][d]), vt = (x@Wv)^T [b][d][t]
// fp32 math, fp16 outputs. One thread per (b,t) row.
// ---------------------------------------------------------------------------
__global__ void __launch_bounds__(256) qkv_proj(const float* __restrict__ x,
                                                const float* __restrict__ Wq,
                                                const float* __restrict__ Wk,
                                                const float* __restrict__ Wv) {
    __shared__ float4 sW[64 * 16];
    const int tid = threadIdx.x;
    const int row = blockIdx.x * 256 + tid;
    const int bb = row >> 12, tt = row & (T_ - 1);

    float xv[64];
    const float4* xr = (const float4*)(x + (size_t)row * D_);
#pragma unroll
    for (int i = 0; i < 16; i++) {
        float4 t = xr[i];
        xv[4 * i + 0] = t.x; xv[4 * i + 1] = t.y;
        xv[4 * i + 2] = t.z; xv[4 * i + 3] = t.w;
    }

#pragma unroll
    for (int m = 0; m < 3; m++) {
        const float* W = (m == 0) ? Wq : (m == 1) ? Wk : Wv;
        const float scale = (m == 0) ? 0.125f : 1.0f;

        __syncthreads();
        for (int i = tid; i < 64 * 16; i += 256) sW[i] = ((const float4*)W)[i];
        __syncthreads();

#pragma unroll
        for (int jc = 0; jc < 4; jc++) {
            float acc[16];
#pragma unroll
            for (int j = 0; j < 16; j++) acc[j] = 0.f;
            for (int d = 0; d < 64; d++) {
                const float xd = xv[d];
                const float4 w0 = sW[d * 16 + jc * 4 + 0];
                const float4 w1 = sW[d * 16 + jc * 4 + 1];
                const float4 w2 = sW[d * 16 + jc * 4 + 2];
                const float4 w3 = sW[d * 16 + jc * 4 + 3];
                acc[0]  += xd * w0.x; acc[1]  += xd * w0.y; acc[2]  += xd * w0.z; acc[3]  += xd * w0.w;
                acc[4]  += xd * w1.x; acc[5]  += xd * w1.y; acc[6]  += xd * w1.z; acc[7]  += xd * w1.w;
                acc[8]  += xd * w2.x; acc[9]  += xd * w2.y; acc[10] += xd * w2.z; acc[11] += xd * w2.w;
                acc[12] += xd * w3.x; acc[13] += xd * w3.y; acc[14] += xd * w3.z; acc[15] += xd * w3.w;
            }
            if (m < 2) {
                __half2* dst = (__half2*)(((m == 0) ? g_q : g_k) + (size_t)row * D_ + jc * 16);
#pragma unroll
                for (int j = 0; j < 8; j++)
                    dst[j] = __floats2half2_rn(acc[2 * j] * scale, acc[2 * j + 1] * scale);
            } else {
                __half* dst = g_vt + (size_t)bb * (D_ * T_) + tt;
#pragma unroll
                for (int j = 0; j < 16; j++)
                    dst[(size_t)(jc * 16 + j) * T_] = __float2half_rn(acc[j]);
            }
        }
    }
}

// ---------------------------------------------------------------------------
// Flash attention, causal, fp16 m16n8k16 MMA. CTA = (qb, b), BR=BC=64,
// 4 warps x 16 Q rows. Double-buffered cp.async K / V^T. Heavy-first.
// ---------------------------------------------------------------------------
__global__ void __launch_bounds__(128, 3) attn(float* __restrict__ out) {
    extern __shared__ __half sm[];
    __half* sK0 = sm;                 // 64 x 72
    __half* sV0 = sm + 1 * BC * STR;
    __half* sK1 = sm + 2 * BC * STR;
    __half* sV1 = sm + 3 * BC * STR;
    __half* sQ  = sm + 4 * BC * STR;  // 64 x 72

    const int b    = blockIdx.y;
    const int qb   = NQB - 1 - (int)blockIdx.x;   // heavy diagonal first
    const int tid  = threadIdx.x;
    const int warp = tid >> 5;
    const int lane = tid & 31;
    const int g    = lane >> 2;
    const int i4   = lane & 3;
    const int rA   = warp * 16 + g;
    const int rB   = rA + 8;

    const __half* Kg  = g_k  + (size_t)b * T_ * D_;
    const __half* Vtg = g_vt + (size_t)b * D_ * T_;
    const __half* Qg  = g_q  + ((size_t)b * T_ + (size_t)qb * BR) * D_;

    // group 1: Q
#pragma unroll
    for (int i = 0; i < 4; i++) {
        const int idx = tid + 128 * i;
        const int r = idx >> 3, c = idx & 7;
        cp16(sQ + r * STR + c * 8, Qg + r * D_ + c * 8);
    }
    CP_COMMIT();
    // group 2: K/V block 0 ; group 3: K/V block 1 (block 1 always in-bounds)
#pragma unroll
    for (int blk = 0; blk < 2; blk++) {
        __half* dK = blk ? sK1 : sK0;
        __half* dV = blk ? sV1 : sV0;
#pragma unroll
        for (int i = 0; i < 4; i++) {
            const int idx = tid + 128 * i;
            const int r = idx >> 3, c = idx & 7;
            cp16(dK + r * STR + c * 8, Kg + (size_t)blk * BC * D_ + r * D_ + c * 8);
            cp16(dV + r * STR + c * 8, Vtg + (size_t)r * T_ + blk * BC + c * 8);
        }
        CP_COMMIT();
    }

    CP_WAIT1();          // Q + block 0 ready
    __syncthreads();

    // Q A-fragments (4 k-chunks of 16)
    uint32_t qf[4][4];
#pragma unroll
    for (int kk = 0; kk < 4; kk++) {
        qf[kk][0] = *(const uint32_t*)(sQ + rA * STR + 16 * kk + 2 * i4);
        qf[kk][1] = *(const uint32_t*)(sQ + rB * STR + 16 * kk + 2 * i4);
        qf[kk][2] = *(const uint32_t*)(sQ + rA * STR + 16 * kk + 8 + 2 * i4);
        qf[kk][3] = *(const uint32_t*)(sQ + rB * STR + 16 * kk + 8 + 2 * i4);
    }

    float o[8][4];
#pragma unroll
    for (int j = 0; j < 8; j++) { o[j][0] = o[j][1] = o[j][2] = o[j][3] = 0.f; }
    float m0 = -1e30f, m1 = -1e30f, l0 = 0.f, l1 = 0.f;

    for (int kb = 0; kb <= qb; kb++) {
        CP_WAIT1();
        __syncthreads();
        const __half* sKb = (kb & 1) ? sK1 : sK0;
        const __half* sVb = (kb & 1) ? sV1 : sV0;

        // ---- S = Q K^T ----
        float s[8][4];
#pragma unroll
        for (int j = 0; j < 8; j++) {
            s[j][0] = s[j][1] = s[j][2] = s[j][3] = 0.f;
            const __half* kr = sKb + (j * 8 + g) * STR;   // banks 4g+i4: conflict-free
#pragma unroll
            for (int kk = 0; kk < 4; kk++) {
                const uint32_t b0 = *(const uint32_t*)(kr + 16 * kk + 2 * i4);
                const uint32_t b1 = *(const uint32_t*)(kr + 16 * kk + 8 + 2 * i4);
                mma16(s[j], qf[kk], b0, b1);
            }
        }

        // ---- causal mask (diagonal block only) ----
        if (kb == qb) {
#pragma unroll
            for (int j = 0; j < 8; j++) {
                const int c0 = j * 8 + 2 * i4;
                if (c0     > rA) s[j][0] = -1e30f;
                if (c0 + 1 > rA) s[j][1] = -1e30f;
                if (c0     > rB) s[j][2] = -1e30f;
                if (c0 + 1 > rB) s[j][3] = -1e30f;
            }
        }

        // ---- online softmax ----
        float mx0 = -1e30f, mx1 = -1e30f;
#pragma unroll
        for (int j = 0; j < 8; j++) {
            mx0 = fmaxf(mx0, fmaxf(s[j][0], s[j][1]));
            mx1 = fmaxf(mx1, fmaxf(s[j][2], s[j][3]));
        }
        mx0 = fmaxf(mx0, __shfl_xor_sync(0xffffffffu, mx0, 1));
        mx0 = fmaxf(mx0, __shfl_xor_sync(0xffffffffu, mx0, 2));
        mx1 = fmaxf(mx1, __shfl_xor_sync(0xffffffffu, mx1, 1));
        mx1 = fmaxf(mx1, __shfl_xor_sync(0xffffffffu, mx1, 2));

        const float mn0 = fmaxf(m0, mx0), mn1 = fmaxf(m1, mx1);
        const float sc0 = __expf(m0 - mn0), sc1 = __expf(m1 - mn1);
        m0 = mn0; m1 = mn1;

        float rs0 = 0.f, rs1 = 0.f;
#pragma unroll
        for (int j = 0; j < 8; j++) {
            s[j][0] = __expf(s[j][0] - m0);
            s[j][1] = __expf(s[j][1] - m0);
            s[j][2] = __expf(s[j][2] - m1);
            s[j][3] = __expf(s[j][3] - m1);
            rs0 += s[j][0] + s[j][1];
            rs1 += s[j][2] + s[j][3];
        }
        rs0 += __shfl_xor_sync(0xffffffffu, rs0, 1);
        rs0 += __shfl_xor_sync(0xffffffffu, rs0, 2);
        rs1 += __shfl_xor_sync(0xffffffffu, rs1, 1);
        rs1 += __shfl_xor_sync(0xffffffffu, rs1, 2);
        l0 = l0 * sc0 + rs0;
        l1 = l1 * sc1 + rs1;

#pragma unroll
        for (int j = 0; j < 8; j++) {
            o[j][0] *= sc0; o[j][1] *= sc0;
            o[j][2] *= sc1; o[j][3] *= sc1;
        }

        // ---- P: C-fragments -> A-fragments, pure register cvt ----
        uint32_t pf[4][4];
#pragma unroll
        for (int kk = 0; kk < 4; kk++) {
            pf[kk][0] = f22h(s[2 * kk][0],     s[2 * kk][1]);
            pf[kk][1] = f22h(s[2 * kk][2],     s[2 * kk][3]);
            pf[kk][2] = f22h(s[2 * kk + 1][0], s[2 * kk + 1][1]);
            pf[kk][3] = f22h(s[2 * kk + 1][2], s[2 * kk + 1][3]);
        }

        // ---- O += P V  (B from V^T tile: rows = d, cols = t) ----
#pragma unroll
        for (int j = 0; j < 8; j++) {
            const __half* vr = sVb + (j * 8 + g) * STR;
#pragma unroll
            for (int kk = 0; kk < 4; kk++) {
                const uint32_t b0 = *(const uint32_t*)(vr + 16 * kk + 2 * i4);
                const uint32_t b1 = *(const uint32_t*)(vr + 16 * kk + 8 + 2 * i4);
                mma16(o[j], pf[kk], b0, b1);
            }
        }

        __syncthreads();   // all warps done reading stage (kb&1) before refill
        if (kb + 2 <= qb) {
            __half* dK = (kb & 1) ? sK1 : sK0;
            __half* dV = (kb & 1) ? sV1 : sV0;
            const __half* Kp = Kg + (size_t)(kb + 2) * BC * D_;
#pragma unroll
            for (int i = 0; i < 4; i++) {
                const int idx = tid + 128 * i;
                const int r = idx >> 3, c = idx & 7;
                cp16(dK + r * STR + c * 8, Kp + r * D_ + c * 8);
                cp16(dV + r * STR + c * 8, Vtg + (size_t)r * T_ + (kb + 2) * BC + c * 8);
            }
        }
        CP_COMMIT();   // uniform group accounting (possibly empty)
    }

    // ---- epilogue: normalize, store. o[j] cols = d = 8j + 2i4 (+1), rows rA/rB ----
    const float inv0 = 1.f / l0, inv1 = 1.f / l1;
    float* Og = out + ((size_t)b * T_ + (size_t)qb * BR) * D_;
#pragma unroll
    for (int j = 0; j < 8; j++) {
        const int c = j * 8 + 2 * i4;
        *(float2*)(Og + rA * D_ + c) = make_float2(o[j][0] * inv0, o[j][1] * inv0);
        *(float2*)(Og + rB * D_ + c) = make_float2(o[j][2] * inv1, o[j][3] * inv1);
    }
}

extern "C" void kernel_launch(void* const* d_in, const int* in_sizes, int n_in,
                              void* d_out, int out_size) {
    const float* x  = (const float*)d_in[0];
    const float* Wq = (const float*)d_in[1];
    const float* Wk = (const float*)d_in[2];
    const float* Wv = (const float*)d_in[3];
    float* out = (float*)d_out;

    qkv_proj<<<(B_ * T_) / 256, 256>>>(x, Wq, Wk, Wv);

    const int smem_bytes = 5 * BC * STR * (int)sizeof(__half);   // 46080 B
    cudaFuncSetAttribute(attn, cudaFuncAttributeMaxDynamicSharedMemorySize, smem_bytes);
    attn<<<dim3(NQB, B_), 128, smem_bytes>>>(out);
}

// round 6
// speedup vs baseline: 2.8725x; 1.3731x over previous
#include <cuda_runtime.h>
#include <cuda_fp16.h>
#include <cstdint>

#define B_   16
#define T_   4096
#define D_   64
#define BR   64
#define BC   64
#define STR  72            // smem row stride (halfs) -> conflict-free frag loads
#define TSTR 136           // transposed v staging stride (halfs)
#define NQB  (T_ / BR)     // 64
#define TILE (BC * STR)    // 4608 halfs per K/V tile

// Projected q (pre-scaled by 1/8), k as [B][T][D]; V transposed as [B][D][T]. All fp16.
__device__ __half g_q [B_ * T_ * D_];
__device__ __half g_k [B_ * T_ * D_];
__device__ __half g_vt[B_ * D_ * T_];

static __device__ __forceinline__ uint32_t f22h(float x, float y) {
    __half2 h = __floats2half2_rn(x, y);
    return *(uint32_t*)&h;
}

// D(16x8,f32) += A(16x16,f16,row) * B(16x8,f16,col)
static __device__ __forceinline__ void mma16(float* c, const uint32_t* a,
                                             uint32_t b0, uint32_t b1) {
    asm volatile(
        "mma.sync.aligned.m16n8k16.row.col.f32.f16.f16.f32 "
        "{%0,%1,%2,%3}, {%4,%5,%6,%7}, {%8,%9}, {%0,%1,%2,%3};\n"
        : "+f"(c[0]), "+f"(c[1]), "+f"(c[2]), "+f"(c[3])
        : "r"(a[0]), "r"(a[1]), "r"(a[2]), "r"(a[3]), "r"(b0), "r"(b1));
}

static __device__ __forceinline__ void cp16(__half* dst, const __half* src) {
    uint32_t s = (uint32_t)__cvta_generic_to_shared(dst);
    asm volatile("cp.async.cg.shared.global [%0], [%1], 16;" :: "r"(s), "l"(src));
}
#define CP_COMMIT() asm volatile("cp.async.commit_group;" ::: "memory")
#define CP_WAIT1()  asm volatile("cp.async.wait_group 1;"  ::: "memory")

// ---------------------------------------------------------------------------
// QKV via fp16 MMA. C = x[128 rows x 64] @ [Wq/8 | Wk | Wv] (64 x 192).
// W^T staged in smem as [n][k]; x tile converted to fp16 A-layout.
// Epilogues route through smem for coalesced stores (v transposed to [d][t]).
// ---------------------------------------------------------------------------
__global__ void __launch_bounds__(256, 2) qkv(const float* __restrict__ x,
                                              const float* __restrict__ Wq,
                                              const float* __restrict__ Wk,
                                              const float* __restrict__ Wv) {
    __shared__ __half sX[128 * STR];   // x tile / output staging (reused)
    __shared__ __half sW[192 * STR];   // W^T, rows n=0..191 (q,k,v), cols k=0..63

    const int tid  = threadIdx.x;
    const int warp = tid >> 5;
    const int lane = tid & 31;
    const int g    = lane >> 2;
    const int i4   = lane & 3;
    const int rA   = warp * 16 + g;
    const int rB   = rA + 8;
    const int row0 = blockIdx.x * 128;
    const int bb   = row0 >> 12;
    const int tt0  = row0 & (T_ - 1);

    // stage W^T (q-scale folded into Wq)
    for (int i = tid; i < 3072; i += 256) {
        const int m = i >> 10, r = (i >> 4) & 63, q4 = i & 15;
        const float* W = (m == 0) ? Wq : (m == 1) ? Wk : Wv;
        const float sc = (m == 0) ? 0.125f : 1.0f;
        float4 w = ((const float4*)(W + r * 64))[q4];
        __half* dn = sW + (m * 64 + q4 * 4) * STR + r;
        dn[0 * STR] = __float2half_rn(w.x * sc);
        dn[1 * STR] = __float2half_rn(w.y * sc);
        dn[2 * STR] = __float2half_rn(w.z * sc);
        dn[3 * STR] = __float2half_rn(w.w * sc);
    }
    // stage x tile as fp16
    for (int i = tid; i < 2048; i += 256) {
        const int r = i >> 4, q4 = i & 15;
        float4 v = ((const float4*)(x + (size_t)(row0 + r) * D_))[q4];
        __half2* d = (__half2*)(sX + r * STR + q4 * 4);
        d[0] = __floats2half2_rn(v.x, v.y);
        d[1] = __floats2half2_rn(v.z, v.w);
    }
    __syncthreads();

    // A fragments (persist across all three passes)
    uint32_t af[4][4];
#pragma unroll
    for (int kk = 0; kk < 4; kk++) {
        af[kk][0] = *(const uint32_t*)(sX + rA * STR + 16 * kk + 2 * i4);
        af[kk][1] = *(const uint32_t*)(sX + rB * STR + 16 * kk + 2 * i4);
        af[kk][2] = *(const uint32_t*)(sX + rA * STR + 16 * kk + 8 + 2 * i4);
        af[kk][3] = *(const uint32_t*)(sX + rB * STR + 16 * kk + 8 + 2 * i4);
    }

#pragma unroll
    for (int m = 0; m < 3; m++) {
        float c[8][4];
#pragma unroll
        for (int j = 0; j < 8; j++) { c[j][0] = c[j][1] = c[j][2] = c[j][3] = 0.f; }
#pragma unroll
        for (int j = 0; j < 8; j++) {
            const __half* wr = sW + (m * 64 + j * 8 + g) * STR;
#pragma unroll
            for (int kk = 0; kk < 4; kk++) {
                const uint32_t b0 = *(const uint32_t*)(wr + 16 * kk + 2 * i4);
                const uint32_t b1 = *(const uint32_t*)(wr + 16 * kk + 8 + 2 * i4);
                mma16(c[j], af[kk], b0, b1);
            }
        }
        __syncthreads();   // prior staging reads (or af loads) complete

        if (m < 2) {
            // stage [t][d], then coalesced 16B stores
#pragma unroll
            for (int j = 0; j < 8; j++) {
                const int cc = j * 8 + 2 * i4;
                *(__half2*)(sX + rA * STR + cc) = __floats2half2_rn(c[j][0], c[j][1]);
                *(__half2*)(sX + rB * STR + cc) = __floats2half2_rn(c[j][2], c[j][3]);
            }
            __syncthreads();
            __half* gdst = (m == 0) ? g_q : g_k;
#pragma unroll
            for (int u = 0; u < 4; u++) {
                const int i = tid + 256 * u;
                const int r = i >> 3, c8 = (i & 7) * 8;
                *(uint4*)(gdst + (size_t)(row0 + r) * D_ + c8) =
                    *(const uint4*)(sX + r * STR + c8);
            }
        } else {
            // stage transposed [d][t], then coalesced 16B stores to g_vt
#pragma unroll
            for (int j = 0; j < 8; j++) {
                const int d0 = j * 8 + 2 * i4;
                sX[(d0    ) * TSTR + rA] = __float2half_rn(c[j][0]);
                sX[(d0 + 1) * TSTR + rA] = __float2half_rn(c[j][1]);
                sX[(d0    ) * TSTR + rB] = __float2half_rn(c[j][2]);
                sX[(d0 + 1) * TSTR + rB] = __float2half_rn(c[j][3]);
            }
            __syncthreads();
            __half* gdst = g_vt + (size_t)bb * (D_ * T_) + tt0;
#pragma unroll
            for (int u = 0; u < 4; u++) {
                const int i = tid + 256 * u;
                const int d = i >> 4, c8 = (i & 15) * 8;
                *(uint4*)(gdst + (size_t)d * T_ + c8) =
                    *(const uint4*)(sX + d * TSTR + c8);
            }
        }
    }
}

// ---------------------------------------------------------------------------
// Flash attention, causal, fp16 m16n8k16. CTA=(qb,b), BR=BC=64, 4 warps.
// Triple-buffered cp.async (distance 2, one barrier/iter). Heavy-first.
// ---------------------------------------------------------------------------
__global__ void __launch_bounds__(128, 3) attn(float* __restrict__ out) {
    extern __shared__ __half sm[];
    __half* sQ = sm + 6 * TILE;

    const int b    = blockIdx.y;
    const int qb   = NQB - 1 - (int)blockIdx.x;   // heavy diagonal first
    const int tid  = threadIdx.x;
    const int warp = tid >> 5;
    const int lane = tid & 31;
    const int g    = lane >> 2;
    const int i4   = lane & 3;
    const int rA   = warp * 16 + g;
    const int rB   = rA + 8;

    const __half* Kg  = g_k  + (size_t)b * T_ * D_;
    const __half* Vtg = g_vt + (size_t)b * D_ * T_;
    const __half* Qg  = g_q  + ((size_t)b * T_ + (size_t)qb * BR) * D_;

    // group 0: Q + K/V block 0
#pragma unroll
    for (int i = 0; i < 4; i++) {
        const int idx = tid + 128 * i;
        const int r = idx >> 3, c = idx & 7;
        cp16(sQ + r * STR + c * 8, Qg + r * D_ + c * 8);
        cp16(sm + r * STR + c * 8, Kg + r * D_ + c * 8);
        cp16(sm + 3 * TILE + r * STR + c * 8, Vtg + (size_t)r * T_ + c * 8);
    }
    CP_COMMIT();
    // group 1: block min(1,qb) -> buffer 1 (clamped fetch keeps groups uniform)
    {
        const int blk = (qb >= 1) ? 1 : 0;
#pragma unroll
        for (int i = 0; i < 4; i++) {
            const int idx = tid + 128 * i;
            const int r = idx >> 3, c = idx & 7;
            cp16(sm + TILE + r * STR + c * 8, Kg + (size_t)blk * BC * D_ + r * D_ + c * 8);
            cp16(sm + 4 * TILE + r * STR + c * 8, Vtg + (size_t)r * T_ + blk * BC + c * 8);
        }
        CP_COMMIT();
    }

    CP_WAIT1();
    __syncthreads();      // Q + block 0 visible

    uint32_t qf[4][4];
#pragma unroll
    for (int kk = 0; kk < 4; kk++) {
        qf[kk][0] = *(const uint32_t*)(sQ + rA * STR + 16 * kk + 2 * i4);
        qf[kk][1] = *(const uint32_t*)(sQ + rB * STR + 16 * kk + 2 * i4);
        qf[kk][2] = *(const uint32_t*)(sQ + rA * STR + 16 * kk + 8 + 2 * i4);
        qf[kk][3] = *(const uint32_t*)(sQ + rB * STR + 16 * kk + 8 + 2 * i4);
    }

    float o[8][4];
#pragma unroll
    for (int j = 0; j < 8; j++) { o[j][0] = o[j][1] = o[j][2] = o[j][3] = 0.f; }
    float m0 = -1e30f, m1 = -1e30f, l0 = 0.f, l1 = 0.f;

    for (int kb = 0; kb <= qb; kb++) {
        if (kb) { CP_WAIT1(); __syncthreads(); }   // block kb ready; prior reads done

        // prefetch block kb+2 (clamped) into buffer (kb+2)%3
        {
            const int blk = (kb + 2 <= qb) ? kb + 2 : qb;
            const int bi = (kb + 2) % 3;
            __half* dK = sm + bi * TILE;
            __half* dV = sm + (3 + bi) * TILE;
            const __half* Kp = Kg + (size_t)blk * BC * D_;
#pragma unroll
            for (int i = 0; i < 4; i++) {
                const int idx = tid + 128 * i;
                const int r = idx >> 3, c = idx & 7;
                cp16(dK + r * STR + c * 8, Kp + r * D_ + c * 8);
                cp16(dV + r * STR + c * 8, Vtg + (size_t)r * T_ + blk * BC + c * 8);
            }
            CP_COMMIT();
        }

        const int ci = kb % 3;
        const __half* sKb = sm + ci * TILE;
        const __half* sVb = sm + (3 + ci) * TILE;

        // ---- S = Q K^T ----
        float s[8][4];
#pragma unroll
        for (int j = 0; j < 8; j++) {
            s[j][0] = s[j][1] = s[j][2] = s[j][3] = 0.f;
            const __half* kr = sKb + (j * 8 + g) * STR;
#pragma unroll
            for (int kk = 0; kk < 4; kk++) {
                const uint32_t b0 = *(const uint32_t*)(kr + 16 * kk + 2 * i4);
                const uint32_t b1 = *(const uint32_t*)(kr + 16 * kk + 8 + 2 * i4);
                mma16(s[j], qf[kk], b0, b1);
            }
        }

        // ---- causal mask (diagonal block only) ----
        if (kb == qb) {
#pragma unroll
            for (int j = 0; j < 8; j++) {
                const int c0 = j * 8 + 2 * i4;
                if (c0     > rA) s[j][0] = -1e30f;
                if (c0 + 1 > rA) s[j][1] = -1e30f;
                if (c0     > rB) s[j][2] = -1e30f;
                if (c0 + 1 > rB) s[j][3] = -1e30f;
            }
        }

        // ---- online softmax: packed half2 max reduce (2 shuffles) ----
        float mx0 = -1e30f, mx1 = -1e30f;
#pragma unroll
        for (int j = 0; j < 8; j++) {
            mx0 = fmaxf(mx0, fmaxf(s[j][0], s[j][1]));
            mx1 = fmaxf(mx1, fmaxf(s[j][2], s[j][3]));
        }
        __half2 hm = __floats2half2_rn(mx0, mx1);
        uint32_t hu = __shfl_xor_sync(0xffffffffu, *(uint32_t*)&hm, 1);
        hm = __hmax2(hm, *(__half2*)&hu);
        hu = __shfl_xor_sync(0xffffffffu, *(uint32_t*)&hm, 2);
        hm = __hmax2(hm, *(__half2*)&hu);
        const float2 mf = __half22float2(hm);

        const float mn0 = fmaxf(m0, mf.x), mn1 = fmaxf(m1, mf.y);
        const float sc0 = __expf(m0 - mn0), sc1 = __expf(m1 - mn1);
        m0 = mn0; m1 = mn1;

        float rs0 = 0.f, rs1 = 0.f;
#pragma unroll
        for (int j = 0; j < 8; j++) {
            s[j][0] = __expf(s[j][0] - m0);
            s[j][1] = __expf(s[j][1] - m0);
            s[j][2] = __expf(s[j][2] - m1);
            s[j][3] = __expf(s[j][3] - m1);
            rs0 += s[j][0] + s[j][1];
            rs1 += s[j][2] + s[j][3];
        }
        l0 = l0 * sc0 + rs0;     // per-thread partial; quad-reduced in epilogue
        l1 = l1 * sc1 + rs1;

#pragma unroll
        for (int j = 0; j < 8; j++) {
            o[j][0] *= sc0; o[j][1] *= sc0;
            o[j][2] *= sc1; o[j][3] *= sc1;
        }

        // ---- P: C-fragments -> A-fragments in registers ----
        uint32_t pf[4][4];
#pragma unroll
        for (int kk = 0; kk < 4; kk++) {
            pf[kk][0] = f22h(s[2 * kk][0],     s[2 * kk][1]);
            pf[kk][1] = f22h(s[2 * kk][2],     s[2 * kk][3]);
            pf[kk][2] = f22h(s[2 * kk + 1][0], s[2 * kk + 1][1]);
            pf[kk][3] = f22h(s[2 * kk + 1][2], s[2 * kk + 1][3]);
        }

        // ---- O += P V ----
#pragma unroll
        for (int j = 0; j < 8; j++) {
            const __half* vr = sVb + (j * 8 + g) * STR;
#pragma unroll
            for (int kk = 0; kk < 4; kk++) {
                const uint32_t b0 = *(const uint32_t*)(vr + 16 * kk + 2 * i4);
                const uint32_t b1 = *(const uint32_t*)(vr + 16 * kk + 8 + 2 * i4);
                mma16(o[j], pf[kk], b0, b1);
            }
        }
    }

    // ---- epilogue: quad-reduce l, normalize, store ----
    l0 += __shfl_xor_sync(0xffffffffu, l0, 1);
    l0 += __shfl_xor_sync(0xffffffffu, l0, 2);
    l1 += __shfl_xor_sync(0xffffffffu, l1, 1);
    l1 += __shfl_xor_sync(0xffffffffu, l1, 2);
    const float inv0 = 1.f / l0, inv1 = 1.f / l1;
    float* Og = out + ((size_t)b * T_ + (size_t)qb * BR) * D_;
#pragma unroll
    for (int j = 0; j < 8; j++) {
        const int c = j * 8 + 2 * i4;
        *(float2*)(Og + rA * D_ + c) = make_float2(o[j][0] * inv0, o[j][1] * inv0);
        *(float2*)(Og + rB * D_ + c) = make_float2(o[j][2] * inv1, o[j][3] * inv1);
    }
}

extern "C" void kernel_launch(void* const* d_in, const int* in_sizes, int n_in,
                              void* d_out, int out_size) {
    const float* x  = (const float*)d_in[0];
    const float* Wq = (const float*)d_in[1];
    const float* Wk = (const float*)d_in[2];
    const float* Wv = (const float*)d_in[3];
    float* out = (float*)d_out;

    qkv<<<(B_ * T_) / 128, 256>>>(x, Wq, Wk, Wv);

    const int smem_bytes = 7 * TILE * (int)sizeof(__half);   // 64512 B
    cudaFuncSetAttribute(attn, cudaFuncAttributeMaxDynamicSharedMemorySize, smem_bytes);
    attn<<<dim3(NQB, B_), 128, smem_bytes>>>(out);
}

// round 7
// speedup vs baseline: 3.2762x; 1.1405x over previous
#include <cuda_runtime.h>
#include <cuda_fp16.h>
#include <cstdint>

#define B_   16
#define T_   4096
#define D_   64
#define BR   64
#define BC   64
#define STR  72            // smem row stride (halfs); 144B rows -> LDSM conflict-free
#define TSTR 136           // transposed v staging stride (halfs)
#define NQB  (T_ / BR)     // 64
#define TILE (BC * STR)    // halfs per K/V tile

// Projected q (pre-scaled by log2(e)/8), k as [B][T][D]; V^T as [B][D][T]. fp16.
__device__ __half g_q [B_ * T_ * D_];
__device__ __half g_k [B_ * T_ * D_];
__device__ __half g_vt[B_ * D_ * T_];

static __device__ __forceinline__ uint32_t f22h(float x, float y) {
    __half2 h = __floats2half2_rn(x, y);
    return *(uint32_t*)&h;
}
static __device__ __forceinline__ float ex2f(float x) {
    float r; asm("ex2.approx.f32 %0, %1;" : "=f"(r) : "f"(x)); return r;
}

// D(16x8,f32) += A(16x16,f16,row) * B(16x8,f16,col)
static __device__ __forceinline__ void mma16(float* c, const uint32_t* a,
                                             uint32_t b0, uint32_t b1) {
    asm volatile(
        "mma.sync.aligned.m16n8k16.row.col.f32.f16.f16.f32 "
        "{%0,%1,%2,%3}, {%4,%5,%6,%7}, {%8,%9}, {%0,%1,%2,%3};\n"
        : "+f"(c[0]), "+f"(c[1]), "+f"(c[2]), "+f"(c[3])
        : "r"(a[0]), "r"(a[1]), "r"(a[2]), "r"(a[3]), "r"(b0), "r"(b1));
}

static __device__ __forceinline__ void ldsm4(uint32_t* r, uint32_t a) {
    asm volatile("ldmatrix.sync.aligned.m8n8.x4.shared.b16 {%0,%1,%2,%3}, [%4];"
                 : "=r"(r[0]), "=r"(r[1]), "=r"(r[2]), "=r"(r[3]) : "r"(a));
}

static __device__ __forceinline__ void cp16(__half* dst, const __half* src) {
    uint32_t s = (uint32_t)__cvta_generic_to_shared(dst);
    asm volatile("cp.async.cg.shared.global [%0], [%1], 16;" :: "r"(s), "l"(src));
}
#define CP_COMMIT() asm volatile("cp.async.commit_group;" ::: "memory")
#define CP_WAIT1()  asm volatile("cp.async.wait_group 1;"  ::: "memory")

// ---------------------------------------------------------------------------
// QKV via fp16 MMA (unchanged structure; q scale now log2(e)/8).
// ---------------------------------------------------------------------------
__global__ void __launch_bounds__(256, 2) qkv(const float* __restrict__ x,
                                              const float* __restrict__ Wq,
                                              const float* __restrict__ Wk,
                                              const float* __restrict__ Wv) {
    __shared__ __half sX[128 * STR];
    __shared__ __half sW[192 * STR];

    const int tid  = threadIdx.x;
    const int warp = tid >> 5;
    const int lane = tid & 31;
    const int g    = lane >> 2;
    const int i4   = lane & 3;
    const int rA   = warp * 16 + g;
    const int rB   = rA + 8;
    const int row0 = blockIdx.x * 128;
    const int bb   = row0 >> 12;
    const int tt0  = row0 & (T_ - 1);

    for (int i = tid; i < 3072; i += 256) {
        const int m = i >> 10, r = (i >> 4) & 63, q4 = i & 15;
        const float* W = (m == 0) ? Wq : (m == 1) ? Wk : Wv;
        const float sc = (m == 0) ? 0.125f * 1.44269504f : 1.0f;
        float4 w = ((const float4*)(W + r * 64))[q4];
        __half* dn = sW + (m * 64 + q4 * 4) * STR + r;
        dn[0 * STR] = __float2half_rn(w.x * sc);
        dn[1 * STR] = __float2half_rn(w.y * sc);
        dn[2 * STR] = __float2half_rn(w.z * sc);
        dn[3 * STR] = __float2half_rn(w.w * sc);
    }
    for (int i = tid; i < 2048; i += 256) {
        const int r = i >> 4, q4 = i & 15;
        float4 v = ((const float4*)(x + (size_t)(row0 + r) * D_))[q4];
        __half2* d = (__half2*)(sX + r * STR + q4 * 4);
        d[0] = __floats2half2_rn(v.x, v.y);
        d[1] = __floats2half2_rn(v.z, v.w);
    }
    __syncthreads();

    uint32_t af[4][4];
#pragma unroll
    for (int kk = 0; kk < 4; kk++) {
        af[kk][0] = *(const uint32_t*)(sX + rA * STR + 16 * kk + 2 * i4);
        af[kk][1] = *(const uint32_t*)(sX + rB * STR + 16 * kk + 2 * i4);
        af[kk][2] = *(const uint32_t*)(sX + rA * STR + 16 * kk + 8 + 2 * i4);
        af[kk][3] = *(const uint32_t*)(sX + rB * STR + 16 * kk + 8 + 2 * i4);
    }

#pragma unroll
    for (int m = 0; m < 3; m++) {
        float c[8][4];
#pragma unroll
        for (int j = 0; j < 8; j++) { c[j][0] = c[j][1] = c[j][2] = c[j][3] = 0.f; }
#pragma unroll
        for (int j = 0; j < 8; j++) {
            const __half* wr = sW + (m * 64 + j * 8 + g) * STR;
#pragma unroll
            for (int kk = 0; kk < 4; kk++) {
                const uint32_t b0 = *(const uint32_t*)(wr + 16 * kk + 2 * i4);
                const uint32_t b1 = *(const uint32_t*)(wr + 16 * kk + 8 + 2 * i4);
                mma16(c[j], af[kk], b0, b1);
            }
        }
        __syncthreads();

        if (m < 2) {
#pragma unroll
            for (int j = 0; j < 8; j++) {
                const int cc = j * 8 + 2 * i4;
                *(__half2*)(sX + rA * STR + cc) = __floats2half2_rn(c[j][0], c[j][1]);
                *(__half2*)(sX + rB * STR + cc) = __floats2half2_rn(c[j][2], c[j][3]);
            }
            __syncthreads();
            __half* gdst = (m == 0) ? g_q : g_k;
#pragma unroll
            for (int u = 0; u < 4; u++) {
                const int i = tid + 256 * u;
                const int r = i >> 3, c8 = (i & 7) * 8;
                *(uint4*)(gdst + (size_t)(row0 + r) * D_ + c8) =
                    *(const uint4*)(sX + r * STR + c8);
            }
        } else {
#pragma unroll
            for (int j = 0; j < 8; j++) {
                const int d0 = j * 8 + 2 * i4;
                sX[(d0    ) * TSTR + rA] = __float2half_rn(c[j][0]);
                sX[(d0 + 1) * TSTR + rA] = __float2half_rn(c[j][1]);
                sX[(d0    ) * TSTR + rB] = __float2half_rn(c[j][2]);
                sX[(d0 + 1) * TSTR + rB] = __float2half_rn(c[j][3]);
            }
            __syncthreads();
            __half* gdst = g_vt + (size_t)bb * (D_ * T_) + tt0;
#pragma unroll
            for (int u = 0; u < 4; u++) {
                const int i = tid + 256 * u;
                const int d = i >> 4, c8 = (i & 15) * 8;
                *(uint4*)(gdst + (size_t)d * T_ + c8) =
                    *(const uint4*)(sX + d * TSTR + c8);
            }
        }
    }
}

// ---------------------------------------------------------------------------
// Flash attention, causal, fp16 m16n8k16 + ldmatrix + exp2 softmax.
// ---------------------------------------------------------------------------
__global__ void __launch_bounds__(128, 3) attn(float* __restrict__ out) {
    extern __shared__ __half sm[];
    __half* sQ = sm + 6 * TILE;

    const int b    = blockIdx.y;
    const int qb   = NQB - 1 - (int)blockIdx.x;   // heavy diagonal first
    const int tid  = threadIdx.x;
    const int warp = tid >> 5;
    const int lane = tid & 31;
    const int g    = lane >> 2;
    const int i4   = lane & 3;
    const int rA   = warp * 16 + g;
    const int rB   = rA + 8;

    const __half* Kg  = g_k  + (size_t)b * T_ * D_;
    const __half* Vtg = g_vt + (size_t)b * D_ * T_;
    const __half* Qg  = g_q  + ((size_t)b * T_ + (size_t)qb * BR) * D_;

    // LDSM lane offsets (bytes). B-tiles: row = lane&7, col16 = lane>>3.
    const uint32_t lB = (uint32_t)((lane & 7) * STR * 2 + (lane >> 3) * 16);
    // Q: matrices = (row-half, col-half) pairs
    const uint32_t lQ = (uint32_t)((warp * 16 + ((lane >> 3) & 1) * 8 + (lane & 7)) * STR * 2
                                   + (lane >> 4) * 16);

    // group 0: Q + K/V block 0
#pragma unroll
    for (int i = 0; i < 4; i++) {
        const int idx = tid + 128 * i;
        const int r = idx >> 3, c = idx & 7;
        cp16(sQ + r * STR + c * 8, Qg + r * D_ + c * 8);
        cp16(sm + r * STR + c * 8, Kg + r * D_ + c * 8);
        cp16(sm + 3 * TILE + r * STR + c * 8, Vtg + (size_t)r * T_ + c * 8);
    }
    CP_COMMIT();
    // group 1: block min(1,qb)
    {
        const int blk = (qb >= 1) ? 1 : 0;
#pragma unroll
        for (int i = 0; i < 4; i++) {
            const int idx = tid + 128 * i;
            const int r = idx >> 3, c = idx & 7;
            cp16(sm + TILE + r * STR + c * 8, Kg + (size_t)blk * BC * D_ + r * D_ + c * 8);
            cp16(sm + 4 * TILE + r * STR + c * 8, Vtg + (size_t)r * T_ + blk * BC + c * 8);
        }
        CP_COMMIT();
    }

    CP_WAIT1();
    __syncthreads();

    uint32_t qf[4][4];
    {
        const uint32_t qbase = (uint32_t)__cvta_generic_to_shared(sQ) + lQ;
#pragma unroll
        for (int kk = 0; kk < 4; kk++) ldsm4(qf[kk], qbase + 32 * kk);
    }

    float o[8][4];
#pragma unroll
    for (int j = 0; j < 8; j++) { o[j][0] = o[j][1] = o[j][2] = o[j][3] = 0.f; }
    float m0 = -1e30f, m1 = -1e30f, l0 = 0.f, l1 = 0.f;

    for (int kb = 0; kb <= qb; kb++) {
        if (kb) { CP_WAIT1(); __syncthreads(); }

        // prefetch block kb+2 (clamped) into buffer (kb+2)%3
        {
            const int blk = (kb + 2 <= qb) ? kb + 2 : qb;
            const int bi = (kb + 2) % 3;
            __half* dK = sm + bi * TILE;
            __half* dV = sm + (3 + bi) * TILE;
            const __half* Kp = Kg + (size_t)blk * BC * D_;
#pragma unroll
            for (int i = 0; i < 4; i++) {
                const int idx = tid + 128 * i;
                const int r = idx >> 3, c = idx & 7;
                cp16(dK + r * STR + c * 8, Kp + r * D_ + c * 8);
                cp16(dV + r * STR + c * 8, Vtg + (size_t)r * T_ + blk * BC + c * 8);
            }
            CP_COMMIT();
        }

        const int ci = kb % 3;
        const uint32_t kbase = (uint32_t)__cvta_generic_to_shared(sm + ci * TILE) + lB;
        const uint32_t vbase = (uint32_t)__cvta_generic_to_shared(sm + (3 + ci) * TILE) + lB;

        // ---- S = Q K^T (B-fragments via ldmatrix) ----
        float s[8][4];
#pragma unroll
        for (int j = 0; j < 8; j++) {
            s[j][0] = s[j][1] = s[j][2] = s[j][3] = 0.f;
            uint32_t bb[8];
            ldsm4(bb,     kbase + (uint32_t)j * (8 * STR * 2));
            ldsm4(bb + 4, kbase + (uint32_t)j * (8 * STR * 2) + 64);
#pragma unroll
            for (int kk = 0; kk < 4; kk++)
                mma16(s[j], qf[kk], bb[2 * kk], bb[2 * kk + 1]);
        }

        // ---- causal mask (diagonal block only) ----
        if (kb == qb) {
#pragma unroll
            for (int j = 0; j < 8; j++) {
                const int c0 = j * 8 + 2 * i4;
                if (c0     > rA) s[j][0] = -1e30f;
                if (c0 + 1 > rA) s[j][1] = -1e30f;
                if (c0     > rB) s[j][2] = -1e30f;
                if (c0 + 1 > rB) s[j][3] = -1e30f;
            }
        }

        // ---- softmax in log2 domain; packed half2 max reduce ----
        float mx0 = -1e30f, mx1 = -1e30f;
#pragma unroll
        for (int j = 0; j < 8; j++) {
            mx0 = fmaxf(mx0, fmaxf(s[j][0], s[j][1]));
            mx1 = fmaxf(mx1, fmaxf(s[j][2], s[j][3]));
        }
        __half2 hm = __floats2half2_rn(mx0, mx1);
        uint32_t hu = __shfl_xor_sync(0xffffffffu, *(uint32_t*)&hm, 1);
        hm = __hmax2(hm, *(__half2*)&hu);
        hu = __shfl_xor_sync(0xffffffffu, *(uint32_t*)&hm, 2);
        hm = __hmax2(hm, *(__half2*)&hu);
        const float2 mf = __half22float2(hm);

        // warp-voted rescale skip (quad-uniform predicates)
        const bool nochg = __all_sync(0xffffffffu, (mf.x <= m0) & (mf.y <= m1));
        if (!nochg) {
            const float mn0 = fmaxf(m0, mf.x), mn1 = fmaxf(m1, mf.y);
            const float sc0 = ex2f(m0 - mn0), sc1 = ex2f(m1 - mn1);
            m0 = mn0; m1 = mn1;
            l0 *= sc0; l1 *= sc1;
#pragma unroll
            for (int j = 0; j < 8; j++) {
                o[j][0] *= sc0; o[j][1] *= sc0;
                o[j][2] *= sc1; o[j][3] *= sc1;
            }
        }

        float rs0 = 0.f, rs1 = 0.f;
#pragma unroll
        for (int j = 0; j < 8; j++) {
            s[j][0] = ex2f(s[j][0] - m0);
            s[j][1] = ex2f(s[j][1] - m0);
            s[j][2] = ex2f(s[j][2] - m1);
            s[j][3] = ex2f(s[j][3] - m1);
            rs0 += s[j][0] + s[j][1];
            rs1 += s[j][2] + s[j][3];
        }
        l0 += rs0;   // per-thread partial; quad-reduced in epilogue
        l1 += rs1;

        // ---- P: C-fragments -> A-fragments in registers ----
        uint32_t pf[4][4];
#pragma unroll
        for (int kk = 0; kk < 4; kk++) {
            pf[kk][0] = f22h(s[2 * kk][0],     s[2 * kk][1]);
            pf[kk][1] = f22h(s[2 * kk][2],     s[2 * kk][3]);
            pf[kk][2] = f22h(s[2 * kk + 1][0], s[2 * kk + 1][1]);
            pf[kk][3] = f22h(s[2 * kk + 1][2], s[2 * kk + 1][3]);
        }

        // ---- O += P V ----
#pragma unroll
        for (int j = 0; j < 8; j++) {
            uint32_t bb[8];
            ldsm4(bb,     vbase + (uint32_t)j * (8 * STR * 2));
            ldsm4(bb + 4, vbase + (uint32_t)j * (8 * STR * 2) + 64);
#pragma unroll
            for (int kk = 0; kk < 4; kk++)
                mma16(o[j], pf[kk], bb[2 * kk], bb[2 * kk + 1]);
        }
    }

    // ---- epilogue: quad-reduce l, normalize, store ----
    l0 += __shfl_xor_sync(0xffffffffu, l0, 1);
    l0 += __shfl_xor_sync(0xffffffffu, l0, 2);
    l1 += __shfl_xor_sync(0xffffffffu, l1, 1);
    l1 += __shfl_xor_sync(0xffffffffu, l1, 2);
    const float inv0 = 1.f / l0, inv1 = 1.f / l1;
    float* Og = out + ((size_t)b * T_ + (size_t)qb * BR) * D_;
#pragma unroll
    for (int j = 0; j < 8; j++) {
        const int c = j * 8 + 2 * i4;
        *(float2*)(Og + rA * D_ + c) = make_float2(o[j][0] * inv0, o[j][1] * inv0);
        *(float2*)(Og + rB * D_ + c) = make_float2(o[j][2] * inv1, o[j][3] * inv1);
    }
}

extern "C" void kernel_launch(void* const* d_in, const int* in_sizes, int n_in,
                              void* d_out, int out_size) {
    const float* x  = (const float*)d_in[0];
    const float* Wq = (const float*)d_in[1];
    const float* Wk = (const float*)d_in[2];
    const float* Wv = (const float*)d_in[3];
    float* out = (float*)d_out;

    qkv<<<(B_ * T_) / 128, 256>>>(x, Wq, Wk, Wv);

    const int smem_bytes = 7 * TILE * (int)sizeof(__half);   // 64512 B
    cudaFuncSetAttribute(attn, cudaFuncAttributeMaxDynamicSharedMemorySize, smem_bytes);
    attn<<<dim3(NQB, B_), 128, smem_bytes>>>(out);
}

// round 8
// speedup vs baseline: 3.3642x; 1.0269x over previous
#include <cuda_runtime.h>
#include <cuda_fp16.h>
#include <cstdint>

#define B_   16
#define T_   4096
#define D_   64
#define BR   64
#define BC   64
#define STR  72            // smem row stride (halfs); 144B rows -> LDSM conflict-free
#define TSTR 136           // transposed v staging stride (halfs)
#define NQB  (T_ / BR)     // 64
#define TILE (BC * STR)    // halfs per K/V tile

// Projected q (pre-scaled by log2(e)/8), k as [B][T][D]; V^T as [B][D][T]. fp16.
__device__ __half g_q [B_ * T_ * D_];
__device__ __half g_k [B_ * T_ * D_];
__device__ __half g_vt[B_ * D_ * T_];

#define ONE2 0x3C003C00u   // half2(1.0, 1.0)

static __device__ __forceinline__ uint32_t f22h(float x, float y) {
    __half2 h = __floats2half2_rn(x, y);
    return *(uint32_t*)&h;
}
static __device__ __forceinline__ float ex2f(float x) {
    float r; asm("ex2.approx.f32 %0, %1;" : "=f"(r) : "f"(x)); return r;
}
static __device__ __forceinline__ uint32_t ex2h2(uint32_t x) {
    uint32_t r; asm("ex2.approx.f16x2 %0, %1;" : "=r"(r) : "r"(x)); return r;
}

// D(16x8,f32) += A(16x16,f16,row) * B(16x8,f16,col)
static __device__ __forceinline__ void mma16(float* c, const uint32_t* a,
                                             uint32_t b0, uint32_t b1) {
    asm volatile(
        "mma.sync.aligned.m16n8k16.row.col.f32.f16.f16.f32 "
        "{%0,%1,%2,%3}, {%4,%5,%6,%7}, {%8,%9}, {%0,%1,%2,%3};\n"
        : "+f"(c[0]), "+f"(c[1]), "+f"(c[2]), "+f"(c[3])
        : "r"(a[0]), "r"(a[1]), "r"(a[2]), "r"(a[3]), "r"(b0), "r"(b1));
}

static __device__ __forceinline__ void ldsm4(uint32_t* r, uint32_t a) {
    asm volatile("ldmatrix.sync.aligned.m8n8.x4.shared.b16 {%0,%1,%2,%3}, [%4];"
                 : "=r"(r[0]), "=r"(r[1]), "=r"(r[2]), "=r"(r[3]) : "r"(a));
}

static __device__ __forceinline__ void cp16(__half* dst, const __half* src) {
    uint32_t s = (uint32_t)__cvta_generic_to_shared(dst);
    asm volatile("cp.async.cg.shared.global [%0], [%1], 16;" :: "r"(s), "l"(src));
}
#define CP_COMMIT() asm volatile("cp.async.commit_group;" ::: "memory")
#define CP_WAIT1()  asm volatile("cp.async.wait_group 1;"  ::: "memory")

// ---------------------------------------------------------------------------
// QKV via fp16 MMA (unchanged; q scale = log2(e)/8).
// ---------------------------------------------------------------------------
__global__ void __launch_bounds__(256, 2) qkv(const float* __restrict__ x,
                                              const float* __restrict__ Wq,
                                              const float* __restrict__ Wk,
                                              const float* __restrict__ Wv) {
    __shared__ __half sX[128 * STR];
    __shared__ __half sW[192 * STR];

    const int tid  = threadIdx.x;
    const int warp = tid >> 5;
    const int lane = tid & 31;
    const int g    = lane >> 2;
    const int i4   = lane & 3;
    const int rA   = warp * 16 + g;
    const int rB   = rA + 8;
    const int row0 = blockIdx.x * 128;
    const int bb   = row0 >> 12;
    const int tt0  = row0 & (T_ - 1);

    for (int i = tid; i < 3072; i += 256) {
        const int m = i >> 10, r = (i >> 4) & 63, q4 = i & 15;
        const float* W = (m == 0) ? Wq : (m == 1) ? Wk : Wv;
        const float sc = (m == 0) ? 0.125f * 1.44269504f : 1.0f;
        float4 w = ((const float4*)(W + r * 64))[q4];
        __half* dn = sW + (m * 64 + q4 * 4) * STR + r;
        dn[0 * STR] = __float2half_rn(w.x * sc);
        dn[1 * STR] = __float2half_rn(w.y * sc);
        dn[2 * STR] = __float2half_rn(w.z * sc);
        dn[3 * STR] = __float2half_rn(w.w * sc);
    }
    for (int i = tid; i < 2048; i += 256) {
        const int r = i >> 4, q4 = i & 15;
        float4 v = ((const float4*)(x + (size_t)(row0 + r) * D_))[q4];
        __half2* d = (__half2*)(sX + r * STR + q4 * 4);
        d[0] = __floats2half2_rn(v.x, v.y);
        d[1] = __floats2half2_rn(v.z, v.w);
    }
    __syncthreads();

    uint32_t af[4][4];
#pragma unroll
    for (int kk = 0; kk < 4; kk++) {
        af[kk][0] = *(const uint32_t*)(sX + rA * STR + 16 * kk + 2 * i4);
        af[kk][1] = *(const uint32_t*)(sX + rB * STR + 16 * kk + 2 * i4);
        af[kk][2] = *(const uint32_t*)(sX + rA * STR + 16 * kk + 8 + 2 * i4);
        af[kk][3] = *(const uint32_t*)(sX + rB * STR + 16 * kk + 8 + 2 * i4);
    }

#pragma unroll
    for (int m = 0; m < 3; m++) {
        float c[8][4];
#pragma unroll
        for (int j = 0; j < 8; j++) { c[j][0] = c[j][1] = c[j][2] = c[j][3] = 0.f; }
#pragma unroll
        for (int j = 0; j < 8; j++) {
            const __half* wr = sW + (m * 64 + j * 8 + g) * STR;
#pragma unroll
            for (int kk = 0; kk < 4; kk++) {
                const uint32_t b0 = *(const uint32_t*)(wr + 16 * kk + 2 * i4);
                const uint32_t b1 = *(const uint32_t*)(wr + 16 * kk + 8 + 2 * i4);
                mma16(c[j], af[kk], b0, b1);
            }
        }
        __syncthreads();

        if (m < 2) {
#pragma unroll
            for (int j = 0; j < 8; j++) {
                const int cc = j * 8 + 2 * i4;
                *(__half2*)(sX + rA * STR + cc) = __floats2half2_rn(c[j][0], c[j][1]);
                *(__half2*)(sX + rB * STR + cc) = __floats2half2_rn(c[j][2], c[j][3]);
            }
            __syncthreads();
            __half* gdst = (m == 0) ? g_q : g_k;
#pragma unroll
            for (int u = 0; u < 4; u++) {
                const int i = tid + 256 * u;
                const int r = i >> 3, c8 = (i & 7) * 8;
                *(uint4*)(gdst + (size_t)(row0 + r) * D_ + c8) =
                    *(const uint4*)(sX + r * STR + c8);
            }
        } else {
#pragma unroll
            for (int j = 0; j < 8; j++) {
                const int d0 = j * 8 + 2 * i4;
                sX[(d0    ) * TSTR + rA] = __float2half_rn(c[j][0]);
                sX[(d0 + 1) * TSTR + rA] = __float2half_rn(c[j][1]);
                sX[(d0    ) * TSTR + rB] = __float2half_rn(c[j][2]);
                sX[(d0 + 1) * TSTR + rB] = __float2half_rn(c[j][3]);
            }
            __syncthreads();
            __half* gdst = g_vt + (size_t)bb * (D_ * T_) + tt0;
#pragma unroll
            for (int u = 0; u < 4; u++) {
                const int i = tid + 256 * u;
                const int d = i >> 4, c8 = (i & 15) * 8;
                *(uint4*)(gdst + (size_t)d * T_ + c8) =
                    *(const uint4*)(sX + d * TSTR + c8);
            }
        }
    }
}

// ---------------------------------------------------------------------------
// Flash attention, causal. fp16 MMA, ldmatrix, f16x2 exp2, MMA row-sums.
// ---------------------------------------------------------------------------
__global__ void __launch_bounds__(128, 3) attn(float* __restrict__ out) {
    extern __shared__ __half sm[];
    __half* sQ = sm + 6 * TILE;

    const int b    = blockIdx.y;
    const int qb   = NQB - 1 - (int)blockIdx.x;   // heavy diagonal first
    const int tid  = threadIdx.x;
    const int warp = tid >> 5;
    const int lane = tid & 31;
    const int g    = lane >> 2;
    const int i4   = lane & 3;
    const int rA   = warp * 16 + g;
    const int rB   = rA + 8;

    const __half* Kg  = g_k  + (size_t)b * T_ * D_;
    const __half* Vtg = g_vt + (size_t)b * D_ * T_;
    const __half* Qg  = g_q  + ((size_t)b * T_ + (size_t)qb * BR) * D_;

    const uint32_t lB = (uint32_t)((lane & 7) * STR * 2 + (lane >> 3) * 16);
    const uint32_t lQ = (uint32_t)((warp * 16 + ((lane >> 3) & 1) * 8 + (lane & 7)) * STR * 2
                                   + (lane >> 4) * 16);

    // group 0: Q + K/V block 0
#pragma unroll
    for (int i = 0; i < 4; i++) {
        const int idx = tid + 128 * i;
        const int r = idx >> 3, c = idx & 7;
        cp16(sQ + r * STR + c * 8, Qg + r * D_ + c * 8);
        cp16(sm + r * STR + c * 8, Kg + r * D_ + c * 8);
        cp16(sm + 3 * TILE + r * STR + c * 8, Vtg + (size_t)r * T_ + c * 8);
    }
    CP_COMMIT();
    // group 1: block min(1,qb)
    {
        const int blk = (qb >= 1) ? 1 : 0;
#pragma unroll
        for (int i = 0; i < 4; i++) {
            const int idx = tid + 128 * i;
            const int r = idx >> 3, c = idx & 7;
            cp16(sm + TILE + r * STR + c * 8, Kg + (size_t)blk * BC * D_ + r * D_ + c * 8);
            cp16(sm + 4 * TILE + r * STR + c * 8, Vtg + (size_t)r * T_ + blk * BC + c * 8);
        }
        CP_COMMIT();
    }

    CP_WAIT1();
    __syncthreads();

    uint32_t qf[4][4];
    {
        const uint32_t qbase = (uint32_t)__cvta_generic_to_shared(sQ) + lQ;
#pragma unroll
        for (int kk = 0; kk < 4; kk++) ldsm4(qf[kk], qbase + 32 * kk);
    }

    float o[8][4];
#pragma unroll
    for (int j = 0; j < 8; j++) { o[j][0] = o[j][1] = o[j][2] = o[j][3] = 0.f; }
    float lacc[4] = {0.f, 0.f, 0.f, 0.f};     // MMA row-sum accumulator
    float m0 = -1e30f, m1 = -1e30f;

    for (int kb = 0; kb <= qb; kb++) {
        if (kb) { CP_WAIT1(); __syncthreads(); }

        // prefetch block kb+2 (clamped) into buffer (kb+2)%3
        {
            const int blk = (kb + 2 <= qb) ? kb + 2 : qb;
            const int bi = (kb + 2) % 3;
            __half* dK = sm + bi * TILE;
            __half* dV = sm + (3 + bi) * TILE;
            const __half* Kp = Kg + (size_t)blk * BC * D_;
#pragma unroll
            for (int i = 0; i < 4; i++) {
                const int idx = tid + 128 * i;
                const int r = idx >> 3, c = idx & 7;
                cp16(dK + r * STR + c * 8, Kp + r * D_ + c * 8);
                cp16(dV + r * STR + c * 8, Vtg + (size_t)r * T_ + blk * BC + c * 8);
            }
            CP_COMMIT();
        }

        const int ci = kb % 3;
        const uint32_t kbase = (uint32_t)__cvta_generic_to_shared(sm + ci * TILE) + lB;
        const uint32_t vbase = (uint32_t)__cvta_generic_to_shared(sm + (3 + ci) * TILE) + lB;

        // ---- S = Q K^T ----
        float s[8][4];
#pragma unroll
        for (int j = 0; j < 8; j++) {
            s[j][0] = s[j][1] = s[j][2] = s[j][3] = 0.f;
            uint32_t bb[8];
            ldsm4(bb,     kbase + (uint32_t)j * (8 * STR * 2));
            ldsm4(bb + 4, kbase + (uint32_t)j * (8 * STR * 2) + 64);
#pragma unroll
            for (int kk = 0; kk < 4; kk++)
                mma16(s[j], qf[kk], bb[2 * kk], bb[2 * kk + 1]);
        }

        // ---- causal mask (diagonal block only) ----
        if (kb == qb) {
#pragma unroll
            for (int j = 0; j < 8; j++) {
                const int c0 = j * 8 + 2 * i4;
                if (c0     > rA) s[j][0] = -1e30f;
                if (c0 + 1 > rA) s[j][1] = -1e30f;
                if (c0     > rB) s[j][2] = -1e30f;
                if (c0 + 1 > rB) s[j][3] = -1e30f;
            }
        }

        // ---- max reduce (packed half2, 2 shuffles) ----
        float mx0 = -1e30f, mx1 = -1e30f;
#pragma unroll
        for (int j = 0; j < 8; j++) {
            mx0 = fmaxf(mx0, fmaxf(s[j][0], s[j][1]));
            mx1 = fmaxf(mx1, fmaxf(s[j][2], s[j][3]));
        }
        __half2 hm = __floats2half2_rn(mx0, mx1);
        uint32_t hu = __shfl_xor_sync(0xffffffffu, *(uint32_t*)&hm, 1);
        hm = __hmax2(hm, *(__half2*)&hu);
        hu = __shfl_xor_sync(0xffffffffu, *(uint32_t*)&hm, 2);
        hm = __hmax2(hm, *(__half2*)&hu);
        const float2 mf = __half22float2(hm);

        // warp-voted rescale skip
        const bool nochg = __all_sync(0xffffffffu, (mf.x <= m0) & (mf.y <= m1));
        if (!nochg) {
            const float mn0 = fmaxf(m0, mf.x), mn1 = fmaxf(m1, mf.y);
            const float sc0 = ex2f(m0 - mn0), sc1 = ex2f(m1 - mn1);
            m0 = mn0; m1 = mn1;
            lacc[0] *= sc0; lacc[2] *= sc1;
#pragma unroll
            for (int j = 0; j < 8; j++) {
                o[j][0] *= sc0; o[j][1] *= sc0;
                o[j][2] *= sc1; o[j][3] *= sc1;
            }
        }

        // ---- P = exp2(s - m): subtract f32, pack, ex2.f16x2 in A-layout ----
        uint32_t pf[4][4];
#pragma unroll
        for (int kk = 0; kk < 4; kk++) {
            pf[kk][0] = ex2h2(f22h(s[2 * kk][0] - m0,     s[2 * kk][1] - m0));
            pf[kk][1] = ex2h2(f22h(s[2 * kk][2] - m1,     s[2 * kk][3] - m1));
            pf[kk][2] = ex2h2(f22h(s[2 * kk + 1][0] - m0, s[2 * kk + 1][1] - m0));
            pf[kk][3] = ex2h2(f22h(s[2 * kk + 1][2] - m1, s[2 * kk + 1][3] - m1));
        }

        // ---- l += P @ ones (exact row sums of fp16 P) ----
#pragma unroll
        for (int kk = 0; kk < 4; kk++)
            mma16(lacc, pf[kk], ONE2, ONE2);

        // ---- O += P V ----
#pragma unroll
        for (int j = 0; j < 8; j++) {
            uint32_t bb[8];
            ldsm4(bb,     vbase + (uint32_t)j * (8 * STR * 2));
            ldsm4(bb + 4, vbase + (uint32_t)j * (8 * STR * 2) + 64);
#pragma unroll
            for (int kk = 0; kk < 4; kk++)
                mma16(o[j], pf[kk], bb[2 * kk], bb[2 * kk + 1]);
        }
    }

    // ---- epilogue: normalize, store (lacc[0]/lacc[2] are full row sums) ----
    const float inv0 = 1.f / lacc[0], inv1 = 1.f / lacc[2];
    float* Og = out + ((size_t)b * T_ + (size_t)qb * BR) * D_;
#pragma unroll
    for (int j = 0; j < 8; j++) {
        const int c = j * 8 + 2 * i4;
        *(float2*)(Og + rA * D_ + c) = make_float2(o[j][0] * inv0, o[j][1] * inv0);
        *(float2*)(Og + rB * D_ + c) = make_float2(o[j][2] * inv1, o[j][3] * inv1);
    }
}

extern "C" void kernel_launch(void* const* d_in, const int* in_sizes, int n_in,
                              void* d_out, int out_size) {
    const float* x  = (const float*)d_in[0];
    const float* Wq = (const float*)d_in[1];
    const float* Wk = (const float*)d_in[2];
    const float* Wv = (const float*)d_in[3];
    float* out = (float*)d_out;

    qkv<<<(B_ * T_) / 128, 256>>>(x, Wq, Wk, Wv);

    const int smem_bytes = 7 * TILE * (int)sizeof(__half);   // 64512 B
    cudaFuncSetAttribute(attn, cudaFuncAttributeMaxDynamicSharedMemorySize, smem_bytes);
    attn<<<dim3(NQB, B_), 128, smem_bytes>>>(out);
}